// round 3
// baseline (speedup 1.0000x reference)
#include <cuda_runtime.h>
#include <math.h>

// Problem constants
#define NT 4096          // tokens (B)
#define DD 1024          // model dim (D)
#define HH 4096          // hidden dim (H)
#define NE 8             // experts
#define TILE_M 128
#define MAXPAIRS (NT*2 + NE*TILE_M)   // 9216 (per-expert segments padded to TILE_M)
#define NTILES (MAXPAIRS/TILE_M)      // 72

// ---------------- scratch (device globals: no allocations allowed) ----------------
__device__ float g_h[(size_t)MAXPAIRS * HH];   // hidden activations, ~151 MB
__device__ float g_o[(size_t)MAXPAIRS * DD];   // expert outputs,     ~38 MB
__device__ int   g_tok_expert[NT*2];
__device__ float g_tok_gate[NT*2];
__device__ int   g_pair_pos[NT*2];             // pair-row index for (token, slot)
__device__ int   g_pair_token[MAXPAIRS];       // token id per pair row (-1 = pad)
__device__ int   g_counts[NE];
__device__ int   g_cursor[NE];
__device__ int   g_offsets[NE+1];
__device__ int   g_tile_expert[NTILES];        // expert per M-tile (-1 = unused)

// ---------------- 1. init ----------------
__global__ void init_k() {
    int t = threadIdx.x;
    if (t < NE) { g_counts[t] = 0; g_cursor[t] = 0; }
}

// ---------------- 2. gating: logits = x @ w_gate, top-2 softmax ----------------
__global__ void gate_k(const float* __restrict__ x, const float* __restrict__ wg) {
    __shared__ float s_wg[DD * NE];            // 32 KB
    for (int i = threadIdx.x; i < DD * NE; i += 256) s_wg[i] = wg[i];
    __syncthreads();
    int warp = threadIdx.x >> 5, lane = threadIdx.x & 31;
    int b = blockIdx.x * 8 + warp;             // 512 blocks * 8 warps = 4096 tokens
    const float* xr = x + (size_t)b * DD;
    float acc[NE];
#pragma unroll
    for (int e = 0; e < NE; e++) acc[e] = 0.f;
    for (int k = lane; k < DD; k += 32) {
        float xv = xr[k];
        const float* w = &s_wg[k * NE];
#pragma unroll
        for (int e = 0; e < NE; e++) acc[e] += xv * w[e];
    }
#pragma unroll
    for (int e = 0; e < NE; e++) {
#pragma unroll
        for (int o = 16; o; o >>= 1) acc[e] += __shfl_xor_sync(0xffffffffu, acc[e], o);
    }
    if (lane == 0) {
        int i0 = 0; float l0 = acc[0];
#pragma unroll
        for (int e = 1; e < NE; e++) if (acc[e] > l0) { l0 = acc[e]; i0 = e; }
        int i1 = -1; float l1 = -3.4e38f;
#pragma unroll
        for (int e = 0; e < NE; e++) if (e != i0 && acc[e] > l1) { l1 = acc[e]; i1 = e; }
        float e1  = expf(l1 - l0);
        float inv = 1.f / (1.f + e1);
        g_tok_expert[b * 2]     = i0;
        g_tok_expert[b * 2 + 1] = i1;
        g_tok_gate[b * 2]       = inv;
        g_tok_gate[b * 2 + 1]   = e1 * inv;
        atomicAdd(&g_counts[i0], 1);
        atomicAdd(&g_counts[i1], 1);
    }
}

// ---------------- 3. offsets: pad expert segments to TILE_M, build tile map ----------------
__global__ void offsets_k() {
    int t = threadIdx.x;
    for (int i = t; i < MAXPAIRS; i += 256) g_pair_token[i] = -1;
    __syncthreads();
    if (t == 0) {
        int off = 0;
        for (int e = 0; e < NE; e++) {
            g_offsets[e] = off;
            int ct = (g_counts[e] + TILE_M - 1) / TILE_M;
            for (int it = 0; it < ct; it++) g_tile_expert[off / TILE_M + it] = e;
            off += ct * TILE_M;
        }
        g_offsets[NE] = off;
        for (int it = off / TILE_M; it < NTILES; it++) g_tile_expert[it] = -1;
    }
}

// ---------------- 4. scatter tokens to pair rows ----------------
__global__ void scatter_k() {
    int b = blockIdx.x * blockDim.x + threadIdx.x;
    if (b >= NT) return;
#pragma unroll
    for (int s = 0; s < 2; s++) {
        int e = g_tok_expert[b * 2 + s];
        int p = atomicAdd(&g_cursor[e], 1);
        int row = g_offsets[e] + p;
        g_pair_token[row] = b;
        g_pair_pos[b * 2 + s] = row;
    }
}

// ---------------- 5. GEMM1: h = relu(X_gathered @ W1[e] + b1[e]) ----------------
// M-tile = 128 (single expert), N-tile = 128, K-step = 16, 256 threads, 8x8/thread
__global__ __launch_bounds__(256, 2)
void gemm1_k(const float* __restrict__ x, const float* __restrict__ W1,
             const float* __restrict__ b1) {
    int e = g_tile_expert[blockIdx.y];
    if (e < 0) return;
    const float* Bg = W1 + (size_t)e * DD * HH;     // K x N, row stride HH
    int m0 = blockIdx.y * TILE_M;
    int n0 = blockIdx.x * 128;
    __shared__ float As[16][128];
    __shared__ float Bs[16][128];
    int t = threadIdx.x;
    int arow = t >> 2, acol = (t & 3) << 2;         // A: 64x(4 float4)/half, 2 halves
    int brow = t >> 5, bcol = (t & 31) << 2;        // B: 8 rows x 32 float4, 2 halves
    int tok0 = g_pair_token[m0 + arow];
    int tok1 = g_pair_token[m0 + arow + 64];
    const float* a0 = (tok0 >= 0) ? x + (size_t)tok0 * DD : 0;
    const float* a1 = (tok1 >= 0) ? x + (size_t)tok1 * DD : 0;
    int tx = t & 15, ty = t >> 4;
    float acc[8][8];
#pragma unroll
    for (int i = 0; i < 8; i++)
#pragma unroll
        for (int j = 0; j < 8; j++) acc[i][j] = 0.f;

    for (int k0 = 0; k0 < DD; k0 += 16) {
        float4 av0 = a0 ? *(const float4*)(a0 + k0 + acol) : make_float4(0.f, 0.f, 0.f, 0.f);
        float4 av1 = a1 ? *(const float4*)(a1 + k0 + acol) : make_float4(0.f, 0.f, 0.f, 0.f);
        As[acol + 0][arow] = av0.x; As[acol + 1][arow] = av0.y;
        As[acol + 2][arow] = av0.z; As[acol + 3][arow] = av0.w;
        As[acol + 0][arow + 64] = av1.x; As[acol + 1][arow + 64] = av1.y;
        As[acol + 2][arow + 64] = av1.z; As[acol + 3][arow + 64] = av1.w;
        const float* bp = Bg + (size_t)(k0 + brow) * HH + n0 + bcol;
        float4 bv0 = *(const float4*)bp;
        float4 bv1 = *(const float4*)(bp + (size_t)8 * HH);
        *(float4*)&Bs[brow][bcol]     = bv0;
        *(float4*)&Bs[brow + 8][bcol] = bv1;
        __syncthreads();
#pragma unroll
        for (int k = 0; k < 16; k++) {
            float a[8], bb[8];
            *(float4*)&a[0]  = *(float4*)&As[k][ty * 8];
            *(float4*)&a[4]  = *(float4*)&As[k][ty * 8 + 4];
            *(float4*)&bb[0] = *(float4*)&Bs[k][tx * 8];
            *(float4*)&bb[4] = *(float4*)&Bs[k][tx * 8 + 4];
#pragma unroll
            for (int i = 0; i < 8; i++)
#pragma unroll
                for (int j = 0; j < 8; j++) acc[i][j] += a[i] * bb[j];
        }
        __syncthreads();
    }
    const float* bias = b1 + (size_t)e * HH + n0 + tx * 8;
#pragma unroll
    for (int i = 0; i < 8; i++) {
        int m = m0 + ty * 8 + i;
        float* hr = g_h + (size_t)m * HH + n0 + tx * 8;
#pragma unroll
        for (int j = 0; j < 8; j += 4) {
            float4 v;
            v.x = fmaxf(acc[i][j + 0] + bias[j + 0], 0.f);
            v.y = fmaxf(acc[i][j + 1] + bias[j + 1], 0.f);
            v.z = fmaxf(acc[i][j + 2] + bias[j + 2], 0.f);
            v.w = fmaxf(acc[i][j + 3] + bias[j + 3], 0.f);
            *(float4*)(hr + j) = v;
        }
    }
}

// ---------------- 6. GEMM2: o = h @ W2[e] + b2[e] ----------------
__global__ __launch_bounds__(256, 2)
void gemm2_k(const float* __restrict__ W2, const float* __restrict__ b2) {
    int e = g_tile_expert[blockIdx.y];
    if (e < 0) return;
    const float* Bg = W2 + (size_t)e * HH * DD;      // K x N, row stride DD
    int m0 = blockIdx.y * TILE_M;
    int n0 = blockIdx.x * 128;
    __shared__ float As[16][128];
    __shared__ float Bs[16][128];
    int t = threadIdx.x;
    int arow = t >> 2, acol = (t & 3) << 2;
    int brow = t >> 5, bcol = (t & 31) << 2;
    const float* a0 = g_h + (size_t)(m0 + arow) * HH;
    const float* a1 = g_h + (size_t)(m0 + arow + 64) * HH;
    int tx = t & 15, ty = t >> 4;
    float acc[8][8];
#pragma unroll
    for (int i = 0; i < 8; i++)
#pragma unroll
        for (int j = 0; j < 8; j++) acc[i][j] = 0.f;

    for (int k0 = 0; k0 < HH; k0 += 16) {
        float4 av0 = *(const float4*)(a0 + k0 + acol);
        float4 av1 = *(const float4*)(a1 + k0 + acol);
        As[acol + 0][arow] = av0.x; As[acol + 1][arow] = av0.y;
        As[acol + 2][arow] = av0.z; As[acol + 3][arow] = av0.w;
        As[acol + 0][arow + 64] = av1.x; As[acol + 1][arow + 64] = av1.y;
        As[acol + 2][arow + 64] = av1.z; As[acol + 3][arow + 64] = av1.w;
        const float* bp = Bg + (size_t)(k0 + brow) * DD + n0 + bcol;
        float4 bv0 = *(const float4*)bp;
        float4 bv1 = *(const float4*)(bp + (size_t)8 * DD);
        *(float4*)&Bs[brow][bcol]     = bv0;
        *(float4*)&Bs[brow + 8][bcol] = bv1;
        __syncthreads();
#pragma unroll
        for (int k = 0; k < 16; k++) {
            float a[8], bb[8];
            *(float4*)&a[0]  = *(float4*)&As[k][ty * 8];
            *(float4*)&a[4]  = *(float4*)&As[k][ty * 8 + 4];
            *(float4*)&bb[0] = *(float4*)&Bs[k][tx * 8];
            *(float4*)&bb[4] = *(float4*)&Bs[k][tx * 8 + 4];
#pragma unroll
            for (int i = 0; i < 8; i++)
#pragma unroll
                for (int j = 0; j < 8; j++) acc[i][j] += a[i] * bb[j];
        }
        __syncthreads();
    }
    const float* bias = b2 + (size_t)e * DD + n0 + tx * 8;
#pragma unroll
    for (int i = 0; i < 8; i++) {
        int m = m0 + ty * 8 + i;
        float* orow = g_o + (size_t)m * DD + n0 + tx * 8;
#pragma unroll
        for (int j = 0; j < 8; j += 4) {
            float4 v;
            v.x = acc[i][j + 0] + bias[j + 0];
            v.y = acc[i][j + 1] + bias[j + 1];
            v.z = acc[i][j + 2] + bias[j + 2];
            v.w = acc[i][j + 3] + bias[j + 3];
            *(float4*)(orow + j) = v;
        }
    }
}

// ---------------- 7. combine: y = log(g0*exp(o0) + g1*exp(o1)) ----------------
__global__ void combine_k(float* __restrict__ y) {
    int idx = blockIdx.x * 256 + threadIdx.x;     // < NT*DD
    int b = idx >> 10;
    int d = idx & 1023;
    int p0 = g_pair_pos[b * 2], p1 = g_pair_pos[b * 2 + 1];
    float g0 = g_tok_gate[b * 2], g1 = g_tok_gate[b * 2 + 1];
    float s = g0 * expf(g_o[(size_t)p0 * DD + d]) + g1 * expf(g_o[(size_t)p1 * DD + d]);
    if (s == 0.f) s = 2.220446049250313e-16f;
    y[idx] = logf(s);
}

// ---------------- 8. balancing loss (deterministic fixed-order reduction) ----------------
__global__ void loss_k(const float* __restrict__ loss_coef, float* __restrict__ out,
                       int out_size) {
    __shared__ float s_imp[256 * NE];
    __shared__ float s_cnt[256 * NE];
    int t = threadIdx.x;
    float imp[NE], cnt[NE];
#pragma unroll
    for (int e = 0; e < NE; e++) { imp[e] = 0.f; cnt[e] = 0.f; }
    for (int b = t; b < NT; b += 256) {
#pragma unroll
        for (int s = 0; s < 2; s++) {
            int e = g_tok_expert[b * 2 + s];
            imp[e] += g_tok_gate[b * 2 + s];
            cnt[e] += 1.f;
        }
    }
#pragma unroll
    for (int e = 0; e < NE; e++) { s_imp[t * NE + e] = imp[e]; s_cnt[t * NE + e] = cnt[e]; }
    __syncthreads();
    for (int stride = 128; stride; stride >>= 1) {
        if (t < stride) {
#pragma unroll
            for (int e = 0; e < NE; e++) {
                s_imp[t * NE + e] += s_imp[(t + stride) * NE + e];
                s_cnt[t * NE + e] += s_cnt[(t + stride) * NE + e];
            }
        }
        __syncthreads();
    }
    if (t == 0) {
        float cv2[2];
        for (int which = 0; which < 2; which++) {
            const float* v = which == 0 ? s_imp : s_cnt;
            float mean = 0.f;
            for (int e = 0; e < NE; e++) mean += v[e];
            mean /= (float)NE;
            float var = 0.f;
            for (int e = 0; e < NE; e++) { float d = v[e] - mean; var += d * d; }
            var /= (float)(NE - 1);                 // unbiased (ddof=1)
            cv2[which] = var / (mean * mean + 1e-10f);
        }
        float loss = (cv2[0] + cv2[1]) * loss_coef[0];
        if (out_size > NT * DD) out[NT * DD] = loss;
    }
}

// ---------------- launch ----------------
extern "C" void kernel_launch(void* const* d_in, const int* in_sizes, int n_in,
                              void* d_out, int out_size) {
    const float* x  = (const float*)d_in[0];   // [4096, 1, 1024]
    const float* wg = (const float*)d_in[1];   // [1024, 8]
    const float* W1 = (const float*)d_in[2];   // [8, 1024, 4096]
    const float* b1 = (const float*)d_in[3];   // [8, 4096]
    const float* W2 = (const float*)d_in[4];   // [8, 4096, 1024]
    const float* b2 = (const float*)d_in[5];   // [8, 1024]
    const float* lc = (const float*)d_in[6];   // scalar
    float* out = (float*)d_out;

    init_k<<<1, 32>>>();
    gate_k<<<512, 256>>>(x, wg);
    offsets_k<<<1, 256>>>();
    scatter_k<<<16, 256>>>();
    gemm1_k<<<dim3(HH / 128, NTILES), 256>>>(x, W1, b1);
    gemm2_k<<<dim3(DD / 128, NTILES), 256>>>(W2, b2);
    combine_k<<<(NT * DD) / 256, 256>>>(out);
    loss_k<<<1, 256>>>(lc, out, out_size);
}

// round 4
// speedup vs baseline: 1.0001x; 1.0001x over previous
#include <cuda_runtime.h>
#include <math.h>

// Problem constants
#define NT 4096          // tokens (B)
#define DD 1024          // model dim (D)
#define HH 4096          // hidden dim (H)
#define NE 8             // experts
#define TILE_M 128
#define MAXPAIRS (NT*2 + NE*TILE_M)   // 9216 (per-expert segments padded to TILE_M)
#define NTILES (MAXPAIRS/TILE_M)      // 72

// ---------------- scratch (device globals: no allocations allowed) ----------------
__device__ float g_h[(size_t)MAXPAIRS * HH];   // hidden activations, ~151 MB
__device__ float g_o[(size_t)MAXPAIRS * DD];   // expert outputs,     ~38 MB
__device__ int   g_tok_expert[NT*2];
__device__ float g_tok_gate[NT*2];
__device__ int   g_pair_pos[NT*2];             // pair-row index for (token, slot)
__device__ int   g_pair_token[MAXPAIRS];       // token id per pair row (-1 = pad)
__device__ int   g_counts[NE];
__device__ int   g_cursor[NE];
__device__ int   g_offsets[NE+1];
__device__ int   g_tile_expert[NTILES];        // expert per M-tile (-1 = unused)

// ---------------- 1. init ----------------
__global__ void init_k() {
    int t = threadIdx.x;
    if (t < NE) { g_counts[t] = 0; g_cursor[t] = 0; }
}

// ---------------- 2. gating: logits = x @ w_gate, top-2 softmax ----------------
__global__ void gate_k(const float* __restrict__ x, const float* __restrict__ wg) {
    __shared__ float s_wg[DD * NE];            // 32 KB
    for (int i = threadIdx.x; i < DD * NE; i += 256) s_wg[i] = wg[i];
    __syncthreads();
    int warp = threadIdx.x >> 5, lane = threadIdx.x & 31;
    int b = blockIdx.x * 8 + warp;             // 512 blocks * 8 warps = 4096 tokens
    const float* xr = x + (size_t)b * DD;
    float acc[NE];
#pragma unroll
    for (int e = 0; e < NE; e++) acc[e] = 0.f;
    for (int k = lane; k < DD; k += 32) {
        float xv = xr[k];
        const float* w = &s_wg[k * NE];
#pragma unroll
        for (int e = 0; e < NE; e++) acc[e] += xv * w[e];
    }
#pragma unroll
    for (int e = 0; e < NE; e++) {
#pragma unroll
        for (int o = 16; o; o >>= 1) acc[e] += __shfl_xor_sync(0xffffffffu, acc[e], o);
    }
    if (lane == 0) {
        int i0 = 0; float l0 = acc[0];
#pragma unroll
        for (int e = 1; e < NE; e++) if (acc[e] > l0) { l0 = acc[e]; i0 = e; }
        int i1 = -1; float l1 = -3.4e38f;
#pragma unroll
        for (int e = 0; e < NE; e++) if (e != i0 && acc[e] > l1) { l1 = acc[e]; i1 = e; }
        float e1  = expf(l1 - l0);
        float inv = 1.f / (1.f + e1);
        g_tok_expert[b * 2]     = i0;
        g_tok_expert[b * 2 + 1] = i1;
        g_tok_gate[b * 2]       = inv;
        g_tok_gate[b * 2 + 1]   = e1 * inv;
        atomicAdd(&g_counts[i0], 1);
        atomicAdd(&g_counts[i1], 1);
    }
}

// ---------------- 3. offsets: pad expert segments to TILE_M, build tile map ----------------
__global__ void offsets_k() {
    int t = threadIdx.x;
    for (int i = t; i < MAXPAIRS; i += 256) g_pair_token[i] = -1;
    __syncthreads();
    if (t == 0) {
        int off = 0;
        for (int e = 0; e < NE; e++) {
            g_offsets[e] = off;
            int ct = (g_counts[e] + TILE_M - 1) / TILE_M;
            for (int it = 0; it < ct; it++) g_tile_expert[off / TILE_M + it] = e;
            off += ct * TILE_M;
        }
        g_offsets[NE] = off;
        for (int it = off / TILE_M; it < NTILES; it++) g_tile_expert[it] = -1;
    }
}

// ---------------- 4. scatter tokens to pair rows ----------------
__global__ void scatter_k() {
    int b = blockIdx.x * blockDim.x + threadIdx.x;
    if (b >= NT) return;
#pragma unroll
    for (int s = 0; s < 2; s++) {
        int e = g_tok_expert[b * 2 + s];
        int p = atomicAdd(&g_cursor[e], 1);
        int row = g_offsets[e] + p;
        g_pair_token[row] = b;
        g_pair_pos[b * 2 + s] = row;
    }
}

// ---------------- 5. GEMM1: h = relu(X_gathered @ W1[e] + b1[e]) ----------------
// M-tile = 128 (single expert), N-tile = 128, K-step = 16, 256 threads, 8x8/thread
__global__ __launch_bounds__(256, 2)
void gemm1_k(const float* __restrict__ x, const float* __restrict__ W1,
             const float* __restrict__ b1) {
    int e = g_tile_expert[blockIdx.y];
    if (e < 0) return;
    const float* Bg = W1 + (size_t)e * DD * HH;     // K x N, row stride HH
    int m0 = blockIdx.y * TILE_M;
    int n0 = blockIdx.x * 128;
    __shared__ float As[16][128];
    __shared__ float Bs[16][128];
    int t = threadIdx.x;
    int arow = t >> 2, acol = (t & 3) << 2;         // A: 64x(4 float4)/half, 2 halves
    int brow = t >> 5, bcol = (t & 31) << 2;        // B: 8 rows x 32 float4, 2 halves
    int tok0 = g_pair_token[m0 + arow];
    int tok1 = g_pair_token[m0 + arow + 64];
    const float* a0 = (tok0 >= 0) ? x + (size_t)tok0 * DD : 0;
    const float* a1 = (tok1 >= 0) ? x + (size_t)tok1 * DD : 0;
    int tx = t & 15, ty = t >> 4;
    float acc[8][8];
#pragma unroll
    for (int i = 0; i < 8; i++)
#pragma unroll
        for (int j = 0; j < 8; j++) acc[i][j] = 0.f;

    for (int k0 = 0; k0 < DD; k0 += 16) {
        float4 av0 = a0 ? *(const float4*)(a0 + k0 + acol) : make_float4(0.f, 0.f, 0.f, 0.f);
        float4 av1 = a1 ? *(const float4*)(a1 + k0 + acol) : make_float4(0.f, 0.f, 0.f, 0.f);
        As[acol + 0][arow] = av0.x; As[acol + 1][arow] = av0.y;
        As[acol + 2][arow] = av0.z; As[acol + 3][arow] = av0.w;
        As[acol + 0][arow + 64] = av1.x; As[acol + 1][arow + 64] = av1.y;
        As[acol + 2][arow + 64] = av1.z; As[acol + 3][arow + 64] = av1.w;
        const float* bp = Bg + (size_t)(k0 + brow) * HH + n0 + bcol;
        float4 bv0 = *(const float4*)bp;
        float4 bv1 = *(const float4*)(bp + (size_t)8 * HH);
        *(float4*)&Bs[brow][bcol]     = bv0;
        *(float4*)&Bs[brow + 8][bcol] = bv1;
        __syncthreads();
#pragma unroll
        for (int k = 0; k < 16; k++) {
            float a[8], bb[8];
            *(float4*)&a[0]  = *(float4*)&As[k][ty * 8];
            *(float4*)&a[4]  = *(float4*)&As[k][ty * 8 + 4];
            *(float4*)&bb[0] = *(float4*)&Bs[k][tx * 8];
            *(float4*)&bb[4] = *(float4*)&Bs[k][tx * 8 + 4];
#pragma unroll
            for (int i = 0; i < 8; i++)
#pragma unroll
                for (int j = 0; j < 8; j++) acc[i][j] += a[i] * bb[j];
        }
        __syncthreads();
    }
    const float* bias = b1 + (size_t)e * HH + n0 + tx * 8;
#pragma unroll
    for (int i = 0; i < 8; i++) {
        int m = m0 + ty * 8 + i;
        float* hr = g_h + (size_t)m * HH + n0 + tx * 8;
#pragma unroll
        for (int j = 0; j < 8; j += 4) {
            float4 v;
            v.x = fmaxf(acc[i][j + 0] + bias[j + 0], 0.f);
            v.y = fmaxf(acc[i][j + 1] + bias[j + 1], 0.f);
            v.z = fmaxf(acc[i][j + 2] + bias[j + 2], 0.f);
            v.w = fmaxf(acc[i][j + 3] + bias[j + 3], 0.f);
            *(float4*)(hr + j) = v;
        }
    }
}

// ---------------- 6. GEMM2: o = h @ W2[e] + b2[e] ----------------
__global__ __launch_bounds__(256, 2)
void gemm2_k(const float* __restrict__ W2, const float* __restrict__ b2) {
    int e = g_tile_expert[blockIdx.y];
    if (e < 0) return;
    const float* Bg = W2 + (size_t)e * HH * DD;      // K x N, row stride DD
    int m0 = blockIdx.y * TILE_M;
    int n0 = blockIdx.x * 128;
    __shared__ float As[16][128];
    __shared__ float Bs[16][128];
    int t = threadIdx.x;
    int arow = t >> 2, acol = (t & 3) << 2;
    int brow = t >> 5, bcol = (t & 31) << 2;
    const float* a0 = g_h + (size_t)(m0 + arow) * HH;
    const float* a1 = g_h + (size_t)(m0 + arow + 64) * HH;
    int tx = t & 15, ty = t >> 4;
    float acc[8][8];
#pragma unroll
    for (int i = 0; i < 8; i++)
#pragma unroll
        for (int j = 0; j < 8; j++) acc[i][j] = 0.f;

    for (int k0 = 0; k0 < HH; k0 += 16) {
        float4 av0 = *(const float4*)(a0 + k0 + acol);
        float4 av1 = *(const float4*)(a1 + k0 + acol);
        As[acol + 0][arow] = av0.x; As[acol + 1][arow] = av0.y;
        As[acol + 2][arow] = av0.z; As[acol + 3][arow] = av0.w;
        As[acol + 0][arow + 64] = av1.x; As[acol + 1][arow + 64] = av1.y;
        As[acol + 2][arow + 64] = av1.z; As[acol + 3][arow + 64] = av1.w;
        const float* bp = Bg + (size_t)(k0 + brow) * DD + n0 + bcol;
        float4 bv0 = *(const float4*)bp;
        float4 bv1 = *(const float4*)(bp + (size_t)8 * DD);
        *(float4*)&Bs[brow][bcol]     = bv0;
        *(float4*)&Bs[brow + 8][bcol] = bv1;
        __syncthreads();
#pragma unroll
        for (int k = 0; k < 16; k++) {
            float a[8], bb[8];
            *(float4*)&a[0]  = *(float4*)&As[k][ty * 8];
            *(float4*)&a[4]  = *(float4*)&As[k][ty * 8 + 4];
            *(float4*)&bb[0] = *(float4*)&Bs[k][tx * 8];
            *(float4*)&bb[4] = *(float4*)&Bs[k][tx * 8 + 4];
#pragma unroll
            for (int i = 0; i < 8; i++)
#pragma unroll
                for (int j = 0; j < 8; j++) acc[i][j] += a[i] * bb[j];
        }
        __syncthreads();
    }
    const float* bias = b2 + (size_t)e * DD + n0 + tx * 8;
#pragma unroll
    for (int i = 0; i < 8; i++) {
        int m = m0 + ty * 8 + i;
        float* orow = g_o + (size_t)m * DD + n0 + tx * 8;
#pragma unroll
        for (int j = 0; j < 8; j += 4) {
            float4 v;
            v.x = acc[i][j + 0] + bias[j + 0];
            v.y = acc[i][j + 1] + bias[j + 1];
            v.z = acc[i][j + 2] + bias[j + 2];
            v.w = acc[i][j + 3] + bias[j + 3];
            *(float4*)(orow + j) = v;
        }
    }
}

// ---------------- 7. combine: y = log(g0*exp(o0) + g1*exp(o1)) ----------------
__global__ void combine_k(float* __restrict__ y) {
    int idx = blockIdx.x * 256 + threadIdx.x;     // < NT*DD
    int b = idx >> 10;
    int d = idx & 1023;
    int p0 = g_pair_pos[b * 2], p1 = g_pair_pos[b * 2 + 1];
    float g0 = g_tok_gate[b * 2], g1 = g_tok_gate[b * 2 + 1];
    float s = g0 * expf(g_o[(size_t)p0 * DD + d]) + g1 * expf(g_o[(size_t)p1 * DD + d]);
    if (s == 0.f) s = 2.220446049250313e-16f;
    y[idx] = logf(s);
}

// ---------------- 8. balancing loss (deterministic fixed-order reduction) ----------------
__global__ void loss_k(const float* __restrict__ loss_coef, float* __restrict__ out,
                       int out_size) {
    __shared__ float s_imp[256 * NE];
    __shared__ float s_cnt[256 * NE];
    int t = threadIdx.x;
    float imp[NE], cnt[NE];
#pragma unroll
    for (int e = 0; e < NE; e++) { imp[e] = 0.f; cnt[e] = 0.f; }
    for (int b = t; b < NT; b += 256) {
#pragma unroll
        for (int s = 0; s < 2; s++) {
            int e = g_tok_expert[b * 2 + s];
            imp[e] += g_tok_gate[b * 2 + s];
            cnt[e] += 1.f;
        }
    }
#pragma unroll
    for (int e = 0; e < NE; e++) { s_imp[t * NE + e] = imp[e]; s_cnt[t * NE + e] = cnt[e]; }
    __syncthreads();
    for (int stride = 128; stride; stride >>= 1) {
        if (t < stride) {
#pragma unroll
            for (int e = 0; e < NE; e++) {
                s_imp[t * NE + e] += s_imp[(t + stride) * NE + e];
                s_cnt[t * NE + e] += s_cnt[(t + stride) * NE + e];
            }
        }
        __syncthreads();
    }
    if (t == 0) {
        float cv2[2];
        for (int which = 0; which < 2; which++) {
            const float* v = which == 0 ? s_imp : s_cnt;
            float mean = 0.f;
            for (int e = 0; e < NE; e++) mean += v[e];
            mean /= (float)NE;
            float var = 0.f;
            for (int e = 0; e < NE; e++) { float d = v[e] - mean; var += d * d; }
            var /= (float)(NE - 1);                 // unbiased (ddof=1)
            cv2[which] = var / (mean * mean + 1e-10f);
        }
        float loss = (cv2[0] + cv2[1]) * loss_coef[0];
        if (out_size > NT * DD) out[NT * DD] = loss;
    }
}

// ---------------- launch ----------------
extern "C" void kernel_launch(void* const* d_in, const int* in_sizes, int n_in,
                              void* d_out, int out_size) {
    const float* x  = (const float*)d_in[0];   // [4096, 1, 1024]
    const float* wg = (const float*)d_in[1];   // [1024, 8]
    const float* W1 = (const float*)d_in[2];   // [8, 1024, 4096]
    const float* b1 = (const float*)d_in[3];   // [8, 4096]
    const float* W2 = (const float*)d_in[4];   // [8, 4096, 1024]
    const float* b2 = (const float*)d_in[5];   // [8, 1024]
    const float* lc = (const float*)d_in[6];   // scalar
    float* out = (float*)d_out;

    init_k<<<1, 32>>>();
    gate_k<<<512, 256>>>(x, wg);
    offsets_k<<<1, 256>>>();
    scatter_k<<<16, 256>>>();
    gemm1_k<<<dim3(HH / 128, NTILES), 256>>>(x, W1, b1);
    gemm2_k<<<dim3(DD / 128, NTILES), 256>>>(W2, b2);
    combine_k<<<(NT * DD) / 256, 256>>>(out);
    loss_k<<<1, 256>>>(lc, out, out_size);
}

// round 7
// speedup vs baseline: 1.0970x; 1.0969x over previous
#include <cuda_runtime.h>
#include <cuda_bf16.h>
#include <math.h>
#include <stdint.h>

#define NT 4096
#define DD 1024
#define HH 4096
#define NE 8
#define TILE_M 128
#define MAXPAIRS (NT*2 + NE*TILE_M)   // 9216
#define NTILES (MAXPAIRS/TILE_M)      // 72
#define KC 32                          // K chunk
#define ROWB 80                        // smem row stride bytes (32 bf16 + pad)

// ---------------- scratch ----------------
__device__ float g_h[(size_t)MAXPAIRS * HH];
__device__ float g_o[(size_t)MAXPAIRS * DD];
__device__ __nv_bfloat16 g_w1t_hi[(size_t)NE * HH * DD];  // [E][N=H][K=D]
__device__ __nv_bfloat16 g_w1t_lo[(size_t)NE * HH * DD];
__device__ __nv_bfloat16 g_w2t_hi[(size_t)NE * DD * HH];  // [E][N=D][K=H]
__device__ __nv_bfloat16 g_w2t_lo[(size_t)NE * DD * HH];
__device__ int   g_tok_expert[NT*2];
__device__ float g_tok_gate[NT*2];
__device__ int   g_pair_pos[NT*2];
__device__ int   g_pair_token[MAXPAIRS];
__device__ int   g_counts[NE];
__device__ int   g_cursor[NE];
__device__ int   g_offsets[NE+1];
__device__ int   g_tile_expert[NTILES];

// ---------------- small kernels ----------------
__global__ void init_k() {
    int t = threadIdx.x;
    if (t < NE) { g_counts[t] = 0; g_cursor[t] = 0; }
}

__global__ void gate_k(const float* __restrict__ x, const float* __restrict__ wg) {
    __shared__ float s_wg[DD * NE];
    for (int i = threadIdx.x; i < DD * NE; i += 256) s_wg[i] = wg[i];
    __syncthreads();
    int warp = threadIdx.x >> 5, lane = threadIdx.x & 31;
    int b = blockIdx.x * 8 + warp;
    const float* xr = x + (size_t)b * DD;
    float acc[NE];
#pragma unroll
    for (int e = 0; e < NE; e++) acc[e] = 0.f;
    for (int k = lane; k < DD; k += 32) {
        float xv = xr[k];
        const float* w = &s_wg[k * NE];
#pragma unroll
        for (int e = 0; e < NE; e++) acc[e] += xv * w[e];
    }
#pragma unroll
    for (int e = 0; e < NE; e++) {
#pragma unroll
        for (int o = 16; o; o >>= 1) acc[e] += __shfl_xor_sync(0xffffffffu, acc[e], o);
    }
    if (lane == 0) {
        int i0 = 0; float l0 = acc[0];
#pragma unroll
        for (int e = 1; e < NE; e++) if (acc[e] > l0) { l0 = acc[e]; i0 = e; }
        int i1 = -1; float l1 = -3.4e38f;
#pragma unroll
        for (int e = 0; e < NE; e++) if (e != i0 && acc[e] > l1) { l1 = acc[e]; i1 = e; }
        float e1  = expf(l1 - l0);
        float inv = 1.f / (1.f + e1);
        g_tok_expert[b*2] = i0;  g_tok_expert[b*2+1] = i1;
        g_tok_gate[b*2]   = inv; g_tok_gate[b*2+1]   = e1 * inv;
        atomicAdd(&g_counts[i0], 1);
        atomicAdd(&g_counts[i1], 1);
    }
}

__global__ void offsets_k() {
    int t = threadIdx.x;
    for (int i = t; i < MAXPAIRS; i += 256) g_pair_token[i] = -1;
    __syncthreads();
    if (t == 0) {
        int off = 0;
        for (int e = 0; e < NE; e++) {
            g_offsets[e] = off;
            int ct = (g_counts[e] + TILE_M - 1) / TILE_M;
            for (int it = 0; it < ct; it++) g_tile_expert[off / TILE_M + it] = e;
            off += ct * TILE_M;
        }
        g_offsets[NE] = off;
        for (int it = off / TILE_M; it < NTILES; it++) g_tile_expert[it] = -1;
    }
}

__global__ void scatter_k() {
    int b = blockIdx.x * blockDim.x + threadIdx.x;
    if (b >= NT) return;
#pragma unroll
    for (int s = 0; s < 2; s++) {
        int e = g_tok_expert[b*2+s];
        int p = atomicAdd(&g_cursor[e], 1);
        int row = g_offsets[e] + p;
        g_pair_token[row] = b;
        g_pair_pos[b*2+s] = row;
    }
}

// ---------------- weight transpose + hi/lo split: [E][K][N] f32 -> [E][N][K] bf16 ----------------
template<bool W1SEL>
__global__ void trans_split_k(const float* __restrict__ in) {
    constexpr int K = W1SEL ? DD : HH;
    constexpr int N = W1SEL ? HH : DD;
    __nv_bfloat16* ohi = W1SEL ? g_w1t_hi : g_w2t_hi;
    __nv_bfloat16* olo = W1SEL ? g_w1t_lo : g_w2t_lo;
    __shared__ float tile[32][33];
    int e = blockIdx.z;
    int k0 = blockIdx.y * 32, n0 = blockIdx.x * 32;
    const float* src = in + ((size_t)e * K + k0) * N + n0;
    for (int i = threadIdx.y; i < 32; i += 8)
        tile[i][threadIdx.x] = src[(size_t)i * N + threadIdx.x];
    __syncthreads();
    size_t obase = ((size_t)e * N + n0) * K + k0;
    for (int i = threadIdx.y; i < 32; i += 8) {
        float v = tile[threadIdx.x][i];
        __nv_bfloat16 h = __float2bfloat16(v);
        ohi[obase + (size_t)i * K + threadIdx.x] = h;
        olo[obase + (size_t)i * K + threadIdx.x] = __float2bfloat16(v - __bfloat162float(h));
    }
}

// ---------------- mma.sync grouped GEMM ----------------
#define MMA_OP(c, a0,a1,a2,a3, b0,b1) \
  asm volatile("mma.sync.aligned.m16n8k16.row.col.f32.bf16.bf16.f32 " \
    "{%0,%1,%2,%3}, {%4,%5,%6,%7}, {%8,%9}, {%0,%1,%2,%3};" \
    : "+f"((c)[0]), "+f"((c)[1]), "+f"((c)[2]), "+f"((c)[3]) \
    : "r"(a0), "r"(a1), "r"(a2), "r"(a3), "r"(b0), "r"(b1))

// dyn smem per stage: A_hi(10240) A_lo(10240) B_hi(10240) B_lo(10240) = 40960; 2 stages
#define SM_AHI(s) ((s)*40960)
#define SM_ALO(s) ((s)*40960 + 10240)
#define SM_BHI(s) ((s)*40960 + 20480)
#define SM_BLO(s) ((s)*40960 + 30720)
#define SMEM_G 81920

template<bool FIRST>
__global__ __launch_bounds__(256, 1)
void gemm_mma(const float* __restrict__ Ain, const float* __restrict__ bias_g) {
    constexpr int KTOT = FIRST ? DD : HH;
    constexpr int NTOT = FIRST ? HH : DD;
    constexpr int NC = KTOT / KC;
    int mt = blockIdx.y;
    int e = g_tile_expert[mt];
    if (e < 0) return;
    const __nv_bfloat16* WhB = FIRST ? g_w1t_hi : g_w2t_hi;
    const __nv_bfloat16* WlB = FIRST ? g_w1t_lo : g_w2t_lo;
    float* Cout = FIRST ? g_h : g_o;

    extern __shared__ char sm[];
    __shared__ const float* s_ap[TILE_M];
    int tid = threadIdx.x;
    int m0 = mt * TILE_M, n0 = blockIdx.x * 128;
    if (tid < TILE_M) {
        if (FIRST) {
            int tok = g_pair_token[m0 + tid];
            s_ap[tid] = (tok >= 0) ? Ain + (size_t)tok * KTOT : (const float*)0;
        } else {
            // FIX: reference device symbol g_h IN DEVICE CODE (host-side &g_h is invalid)
            s_ap[tid] = g_h + (size_t)(m0 + tid) * KTOT;
        }
    }
    __syncthreads();

    // loader roles: row r (0..127), half hf (0/1) of the 32-wide k-chunk
    int r = tid >> 1, hf = tid & 1;
    const float* arow = s_ap[r];
    const __nv_bfloat16* bhrow = WhB + ((size_t)e * NTOT + n0 + r) * KTOT;
    const __nv_bfloat16* blrow = WlB + ((size_t)e * NTOT + n0 + r) * KTOT;
    uint32_t arowoff = (uint32_t)(r * ROWB + hf * 32);

    int lane = tid & 31, w = tid >> 5;
    int wr = w >> 2, wc = w & 3;          // warp grid 2x4, warp tile 64x32
    int g = lane >> 2, tg = lane & 3;

    float acc[4][4][4];
#pragma unroll
    for (int i = 0; i < 4; i++)
#pragma unroll
        for (int j = 0; j < 4; j++)
#pragma unroll
            for (int q = 0; q < 4; q++) acc[i][j][q] = 0.f;

    float4 fa[4]; uint4 fbh[2], fbl[2];

    auto LOADREGS = [&](int ch) {
        int k0 = ch * KC;
        if (arow) {
            const float4* ap = (const float4*)(arow + k0 + hf * 16);
#pragma unroll
            for (int q = 0; q < 4; q++) fa[q] = ap[q];
        } else {
#pragma unroll
            for (int q = 0; q < 4; q++) fa[q] = make_float4(0.f, 0.f, 0.f, 0.f);
        }
        const uint4* ph = (const uint4*)(bhrow + k0) + hf * 2;
        const uint4* pl = (const uint4*)(blrow + k0) + hf * 2;
        fbh[0] = ph[0]; fbh[1] = ph[1];
        fbl[0] = pl[0]; fbl[1] = pl[1];
    };

    auto STORE = [&](int s) {
        uint32_t hi[8], lo[8];
#pragma unroll
        for (int q = 0; q < 4; q++) {
            float4 v = fa[q];
            __nv_bfloat162 h01 = __floats2bfloat162_rn(v.x, v.y);
            __nv_bfloat162 h23 = __floats2bfloat162_rn(v.z, v.w);
            float2 f01 = __bfloat1622float2(h01);
            float2 f23 = __bfloat1622float2(h23);
            __nv_bfloat162 l01 = __floats2bfloat162_rn(v.x - f01.x, v.y - f01.y);
            __nv_bfloat162 l23 = __floats2bfloat162_rn(v.z - f23.x, v.w - f23.y);
            hi[q*2]   = *(uint32_t*)&h01; hi[q*2+1] = *(uint32_t*)&h23;
            lo[q*2]   = *(uint32_t*)&l01; lo[q*2+1] = *(uint32_t*)&l23;
        }
        uint4* ah = (uint4*)(sm + SM_AHI(s) + arowoff);
        uint4* al = (uint4*)(sm + SM_ALO(s) + arowoff);
        ah[0] = make_uint4(hi[0],hi[1],hi[2],hi[3]); ah[1] = make_uint4(hi[4],hi[5],hi[6],hi[7]);
        al[0] = make_uint4(lo[0],lo[1],lo[2],lo[3]); al[1] = make_uint4(lo[4],lo[5],lo[6],lo[7]);
        uint4* bh = (uint4*)(sm + SM_BHI(s) + arowoff);
        uint4* bl = (uint4*)(sm + SM_BLO(s) + arowoff);
        bh[0] = fbh[0]; bh[1] = fbh[1];
        bl[0] = fbl[0]; bl[1] = fbl[1];
    };

    auto COMPUTE = [&](int s) {
#pragma unroll
        for (int kk = 0; kk < 2; kk++) {
            uint32_t bbase = (uint32_t)((wc*32 + g) * ROWB + kk*32 + tg*4);
            uint32_t bh0[4], bh1[4], bl0[4], bl1[4];
#pragma unroll
            for (int j = 0; j < 4; j++) {
                uint32_t o = bbase + j * 8 * ROWB;
                bh0[j] = *(const uint32_t*)(sm + SM_BHI(s) + o);
                bh1[j] = *(const uint32_t*)(sm + SM_BHI(s) + o + 16);
                bl0[j] = *(const uint32_t*)(sm + SM_BLO(s) + o);
                bl1[j] = *(const uint32_t*)(sm + SM_BLO(s) + o + 16);
            }
            uint32_t abase = (uint32_t)((wr*64 + g) * ROWB + kk*32 + tg*4);
#pragma unroll
            for (int i = 0; i < 4; i++) {
                uint32_t o = abase + i * 16 * ROWB;
                uint32_t ah0 = *(const uint32_t*)(sm + SM_AHI(s) + o);
                uint32_t ah1 = *(const uint32_t*)(sm + SM_AHI(s) + o + 8*ROWB);
                uint32_t ah2 = *(const uint32_t*)(sm + SM_AHI(s) + o + 16);
                uint32_t ah3 = *(const uint32_t*)(sm + SM_AHI(s) + o + 8*ROWB + 16);
                uint32_t al0 = *(const uint32_t*)(sm + SM_ALO(s) + o);
                uint32_t al1 = *(const uint32_t*)(sm + SM_ALO(s) + o + 8*ROWB);
                uint32_t al2 = *(const uint32_t*)(sm + SM_ALO(s) + o + 16);
                uint32_t al3 = *(const uint32_t*)(sm + SM_ALO(s) + o + 8*ROWB + 16);
#pragma unroll
                for (int j = 0; j < 4; j++) {
                    MMA_OP(acc[i][j], ah0, ah1, ah2, ah3, bh0[j], bh1[j]);
                    MMA_OP(acc[i][j], ah0, ah1, ah2, ah3, bl0[j], bl1[j]);
                    MMA_OP(acc[i][j], al0, al1, al2, al3, bh0[j], bh1[j]);
                }
            }
        }
    };

    LOADREGS(0);
    STORE(0);
    __syncthreads();
    for (int ch = 0; ch < NC; ch++) {
        int sg = ch & 1;
        if (ch + 1 < NC) LOADREGS(ch + 1);
        COMPUTE(sg);
        if (ch + 1 < NC) STORE((ch + 1) & 1);
        __syncthreads();
    }

    // epilogue
    const float* bias = bias_g + (size_t)e * NTOT + n0;
#pragma unroll
    for (int i = 0; i < 4; i++) {
        int row0 = m0 + wr*64 + i*16 + g;
#pragma unroll
        for (int j = 0; j < 4; j++) {
            int nc = wc*32 + j*8 + tg*2;
            float b0v = bias[nc], b1v = bias[nc+1];
            float2 v0, v1;
            v0.x = acc[i][j][0] + b0v; v0.y = acc[i][j][1] + b1v;
            v1.x = acc[i][j][2] + b0v; v1.y = acc[i][j][3] + b1v;
            if (FIRST) {
                v0.x = fmaxf(v0.x, 0.f); v0.y = fmaxf(v0.y, 0.f);
                v1.x = fmaxf(v1.x, 0.f); v1.y = fmaxf(v1.y, 0.f);
            }
            *(float2*)(Cout + (size_t)row0 * NTOT + n0 + nc)       = v0;
            *(float2*)(Cout + (size_t)(row0 + 8) * NTOT + n0 + nc) = v1;
        }
    }
}

// ---------------- combine: y = om + log(gm + gn*exp(on-om)) ----------------
__global__ void combine_k(float* __restrict__ y) {
    int idx = blockIdx.x * 256 + threadIdx.x;
    int b = idx >> 10;
    int d = idx & 1023;
    int p0 = g_pair_pos[b*2], p1 = g_pair_pos[b*2+1];
    float g0 = g_tok_gate[b*2], g1 = g_tok_gate[b*2+1];
    float o0 = g_o[(size_t)p0 * DD + d];
    float o1 = g_o[(size_t)p1 * DD + d];
    float om = fmaxf(o0, o1), on = fminf(o0, o1);
    float gm = (o0 >= o1) ? g0 : g1;
    float gn = (o0 >= o1) ? g1 : g0;
    y[idx] = om + __logf(fmaf(gn, __expf(on - om), gm));
}

// ---------------- balancing loss ----------------
__global__ void loss_k(const float* __restrict__ loss_coef, float* __restrict__ out,
                       int out_size) {
    __shared__ float s_imp[256 * NE];
    __shared__ float s_cnt[256 * NE];
    int t = threadIdx.x;
    float imp[NE], cnt[NE];
#pragma unroll
    for (int e = 0; e < NE; e++) { imp[e] = 0.f; cnt[e] = 0.f; }
    for (int b = t; b < NT; b += 256) {
#pragma unroll
        for (int s = 0; s < 2; s++) {
            int e = g_tok_expert[b*2+s];
            imp[e] += g_tok_gate[b*2+s];
            cnt[e] += 1.f;
        }
    }
#pragma unroll
    for (int e = 0; e < NE; e++) { s_imp[t*NE+e] = imp[e]; s_cnt[t*NE+e] = cnt[e]; }
    __syncthreads();
    for (int stride = 128; stride; stride >>= 1) {
        if (t < stride) {
#pragma unroll
            for (int e = 0; e < NE; e++) {
                s_imp[t*NE+e] += s_imp[(t+stride)*NE+e];
                s_cnt[t*NE+e] += s_cnt[(t+stride)*NE+e];
            }
        }
        __syncthreads();
    }
    if (t == 0) {
        float cv2[2];
        for (int which = 0; which < 2; which++) {
            const float* v = which == 0 ? s_imp : s_cnt;
            float mean = 0.f;
            for (int e = 0; e < NE; e++) mean += v[e];
            mean /= (float)NE;
            float var = 0.f;
            for (int e = 0; e < NE; e++) { float d = v[e] - mean; var += d * d; }
            var /= (float)(NE - 1);
            cv2[which] = var / (mean * mean + 1e-10f);
        }
        float loss = (cv2[0] + cv2[1]) * loss_coef[0];
        if (out_size > NT * DD) out[NT * DD] = loss;
    }
}

// ---------------- launch ----------------
extern "C" void kernel_launch(void* const* d_in, const int* in_sizes, int n_in,
                              void* d_out, int out_size) {
    const float* x  = (const float*)d_in[0];
    const float* wg = (const float*)d_in[1];
    const float* W1 = (const float*)d_in[2];
    const float* b1 = (const float*)d_in[3];
    const float* W2 = (const float*)d_in[4];
    const float* b2 = (const float*)d_in[5];
    const float* lc = (const float*)d_in[6];
    float* out = (float*)d_out;

    cudaFuncSetAttribute(gemm_mma<true>,  cudaFuncAttributeMaxDynamicSharedMemorySize, SMEM_G);
    cudaFuncSetAttribute(gemm_mma<false>, cudaFuncAttributeMaxDynamicSharedMemorySize, SMEM_G);

    init_k<<<1, 32>>>();
    gate_k<<<512, 256>>>(x, wg);
    offsets_k<<<1, 256>>>();
    scatter_k<<<16, 256>>>();
    trans_split_k<true ><<<dim3(HH/32, DD/32, NE), dim3(32, 8)>>>(W1);
    trans_split_k<false><<<dim3(DD/32, HH/32, NE), dim3(32, 8)>>>(W2);
    gemm_mma<true ><<<dim3(HH/128, NTILES), 256, SMEM_G>>>(x,   b1);
    gemm_mma<false><<<dim3(DD/128, NTILES), 256, SMEM_G>>>(x,   b2);  // A = g_h (device-side)
    combine_k<<<(NT * DD) / 256, 256>>>(out);
    loss_k<<<1, 256>>>(lc, out, out_size);
}

// round 9
// speedup vs baseline: 2.6491x; 2.4148x over previous
#include <cuda_runtime.h>
#include <cuda_bf16.h>
#include <math.h>
#include <stdint.h>

#define NT 4096
#define DD 1024
#define HH 4096
#define NE 8
#define TILE_M 128
#define MAXPAIRS (NT*2 + NE*TILE_M)   // 9216
#define NTILES (MAXPAIRS/TILE_M)      // 72
#define KC 32                          // K elements per chunk
#define STAGE_B 32768                  // 4 mats * 128 rows * 64B
#define SMEM_G (3*STAGE_B)             // 98304

// ---------------- scratch ----------------
__device__ __nv_bfloat16 g_xhi[(size_t)NT * DD];
__device__ __nv_bfloat16 g_xlo[(size_t)NT * DD];
__device__ __nv_bfloat16 g_hhi[(size_t)MAXPAIRS * HH];
__device__ __nv_bfloat16 g_hlo[(size_t)MAXPAIRS * HH];
__device__ float g_o[(size_t)MAXPAIRS * DD];
__device__ __nv_bfloat16 g_w1t_hi[(size_t)NE * HH * DD];  // [E][N=H][K=D]
__device__ __nv_bfloat16 g_w1t_lo[(size_t)NE * HH * DD];
__device__ __nv_bfloat16 g_w2t_hi[(size_t)NE * DD * HH];  // [E][N=D][K=H]
__device__ __nv_bfloat16 g_w2t_lo[(size_t)NE * DD * HH];
__device__ int   g_tok_expert[NT*2];
__device__ float g_tok_gate[NT*2];
__device__ int   g_pair_pos[NT*2];
__device__ int   g_pair_token[MAXPAIRS];
__device__ int   g_counts[NE];
__device__ int   g_cursor[NE];
__device__ int   g_offsets[NE+1];
__device__ int   g_tile_expert[NTILES];

// ---------------- asm helpers ----------------
__device__ __forceinline__ uint32_t smem_u32(const void* p) {
    uint32_t a;
    asm("{ .reg .u64 t; cvta.to.shared.u64 t, %1; cvt.u32.u64 %0, t; }" : "=r"(a) : "l"(p));
    return a;
}
#define CPA(dst, src, sz) \
    asm volatile("cp.async.cg.shared.global [%0], [%1], 16, %2;" \
        :: "r"(dst), "l"(src), "r"(sz))
#define CPA_COMMIT() asm volatile("cp.async.commit_group;")
#define CPA_WAIT1()  asm volatile("cp.async.wait_group 1;")
#define CPA_WAIT0()  asm volatile("cp.async.wait_group 0;")
#define LDSM4(r0,r1,r2,r3, a) \
    asm volatile("ldmatrix.sync.aligned.m8n8.x4.shared.b16 {%0,%1,%2,%3}, [%4];" \
        : "=r"(r0), "=r"(r1), "=r"(r2), "=r"(r3) : "r"(a))
#define MMA_OP(c, a0,a1,a2,a3, b0,b1) \
  asm volatile("mma.sync.aligned.m16n8k16.row.col.f32.bf16.bf16.f32 " \
    "{%0,%1,%2,%3}, {%4,%5,%6,%7}, {%8,%9}, {%0,%1,%2,%3};" \
    : "+f"((c)[0]), "+f"((c)[1]), "+f"((c)[2]), "+f"((c)[3]) \
    : "r"(a0), "r"(a1), "r"(a2), "r"(a3), "r"(b0), "r"(b1))

// ---------------- small kernels ----------------
__global__ void init_k() {
    int t = threadIdx.x;
    if (t < NE) { g_counts[t] = 0; g_cursor[t] = 0; }
}

__global__ void gate_k(const float* __restrict__ x, const float* __restrict__ wg) {
    __shared__ float s_wg[DD * NE];
    for (int i = threadIdx.x; i < DD * NE; i += 256) s_wg[i] = wg[i];
    __syncthreads();
    int warp = threadIdx.x >> 5, lane = threadIdx.x & 31;
    int b = blockIdx.x * 8 + warp;
    const float* xr = x + (size_t)b * DD;
    float acc[NE];
#pragma unroll
    for (int e = 0; e < NE; e++) acc[e] = 0.f;
    for (int k = lane; k < DD; k += 32) {
        float xv = xr[k];
        const float* w = &s_wg[k * NE];
#pragma unroll
        for (int e = 0; e < NE; e++) acc[e] += xv * w[e];
    }
#pragma unroll
    for (int e = 0; e < NE; e++) {
#pragma unroll
        for (int o = 16; o; o >>= 1) acc[e] += __shfl_xor_sync(0xffffffffu, acc[e], o);
    }
    if (lane == 0) {
        int i0 = 0; float l0 = acc[0];
#pragma unroll
        for (int e = 1; e < NE; e++) if (acc[e] > l0) { l0 = acc[e]; i0 = e; }
        int i1 = -1; float l1 = -3.4e38f;
#pragma unroll
        for (int e = 0; e < NE; e++) if (e != i0 && acc[e] > l1) { l1 = acc[e]; i1 = e; }
        float e1  = expf(l1 - l0);
        float inv = 1.f / (1.f + e1);
        g_tok_expert[b*2] = i0;  g_tok_expert[b*2+1] = i1;
        g_tok_gate[b*2]   = inv; g_tok_gate[b*2+1]   = e1 * inv;
        atomicAdd(&g_counts[i0], 1);
        atomicAdd(&g_counts[i1], 1);
    }
}

__global__ void offsets_k() {
    int t = threadIdx.x;
    for (int i = t; i < MAXPAIRS; i += 256) g_pair_token[i] = -1;
    __syncthreads();
    if (t == 0) {
        int off = 0;
        for (int e = 0; e < NE; e++) {
            g_offsets[e] = off;
            int ct = (g_counts[e] + TILE_M - 1) / TILE_M;
            for (int it = 0; it < ct; it++) g_tile_expert[off / TILE_M + it] = e;
            off += ct * TILE_M;
        }
        g_offsets[NE] = off;
        for (int it = off / TILE_M; it < NTILES; it++) g_tile_expert[it] = -1;
    }
}

__global__ void scatter_k() {
    int b = blockIdx.x * blockDim.x + threadIdx.x;
    if (b >= NT) return;
#pragma unroll
    for (int s = 0; s < 2; s++) {
        int e = g_tok_expert[b*2+s];
        int p = atomicAdd(&g_cursor[e], 1);
        int row = g_offsets[e] + p;
        g_pair_token[row] = b;
        g_pair_pos[b*2+s] = row;
    }
}

// ---------------- x hi/lo split ----------------
__global__ void xsplit_k(const float* __restrict__ x) {
    int idx = blockIdx.x * 256 + threadIdx.x;       // * 4 floats
    float4 v = ((const float4*)x)[idx];
    __nv_bfloat162 h01 = __floats2bfloat162_rn(v.x, v.y);
    __nv_bfloat162 h23 = __floats2bfloat162_rn(v.z, v.w);
    float2 f01 = __bfloat1622float2(h01);
    float2 f23 = __bfloat1622float2(h23);
    __nv_bfloat162 l01 = __floats2bfloat162_rn(v.x - f01.x, v.y - f01.y);
    __nv_bfloat162 l23 = __floats2bfloat162_rn(v.z - f23.x, v.w - f23.y);
    ((uint2*)g_xhi)[idx] = make_uint2(*(uint32_t*)&h01, *(uint32_t*)&h23);
    ((uint2*)g_xlo)[idx] = make_uint2(*(uint32_t*)&l01, *(uint32_t*)&l23);
}

// ---------------- weight transpose + hi/lo split: [E][K][N] f32 -> [E][N][K] bf16 ----------------
template<bool W1SEL>
__global__ void trans_split_k(const float* __restrict__ in) {
    constexpr int K = W1SEL ? DD : HH;
    constexpr int N = W1SEL ? HH : DD;
    __nv_bfloat16* ohi = W1SEL ? g_w1t_hi : g_w2t_hi;
    __nv_bfloat16* olo = W1SEL ? g_w1t_lo : g_w2t_lo;
    __shared__ float tile[32][33];
    int e = blockIdx.z;
    int k0 = blockIdx.y * 32, n0 = blockIdx.x * 32;
    const float* src = in + ((size_t)e * K + k0) * N + n0;
    for (int i = threadIdx.y; i < 32; i += 8)
        tile[i][threadIdx.x] = src[(size_t)i * N + threadIdx.x];
    __syncthreads();
    size_t obase = ((size_t)e * N + n0) * K + k0;
    for (int i = threadIdx.y; i < 32; i += 8) {
        float v = tile[threadIdx.x][i];
        __nv_bfloat16 h = __float2bfloat16(v);
        ohi[obase + (size_t)i * K + threadIdx.x] = h;
        olo[obase + (size_t)i * K + threadIdx.x] = __float2bfloat16(v - __bfloat162float(h));
    }
}

// ---------------- cp.async + ldmatrix grouped GEMM ----------------
// smem stage layout (32KB): A_hi[128][64B] | A_lo | B_hi | B_lo, 64B rows,
// 16B slot swizzle: byte = row*64 + ((c ^ ((row>>1)&3))<<4)
template<bool FIRST>
__global__ __launch_bounds__(256, 2)
void gemm_cp(const float* __restrict__ bias_g) {
    constexpr int KTOT = FIRST ? DD : HH;
    constexpr int NTOT = FIRST ? HH : DD;
    constexpr int NC = KTOT / KC;
    int mt = blockIdx.y;
    int e = g_tile_expert[mt];
    if (e < 0) return;

    extern __shared__ char sm[];
    uint32_t sb = smem_u32(sm);
    int tid = threadIdx.x, lane = tid & 31, w = tid >> 5;
    int wr = w >> 2, wc = w & 3;                    // warp grid 2x4, warp tile 64x32
    int m0 = mt * TILE_M, n0 = blockIdx.x * 128;

    // ---- loader setup: thread owns rows (tid>>2) and 64+(tid>>2), 16B slot tid&3 ----
    int lr0 = tid >> 2, lr1 = 64 + (tid >> 2);
    int lc = tid & 3;
    const char *pA0, *pA1, *pB0, *pB1;
    uint32_t szA0 = 16, szA1 = 16;
    long long dA, dB;
    if (FIRST) {
        dA = (const char*)g_xlo - (const char*)g_xhi;
        int t0 = g_pair_token[m0 + lr0], t1 = g_pair_token[m0 + lr1];
        pA0 = (const char*)g_xhi + ((t0 >= 0 ? (size_t)t0 : 0) * DD) * 2 + lc * 16;
        pA1 = (const char*)g_xhi + ((t1 >= 0 ? (size_t)t1 : 0) * DD) * 2 + lc * 16;
        if (t0 < 0) szA0 = 0;
        if (t1 < 0) szA1 = 0;
        dB = (const char*)g_w1t_lo - (const char*)g_w1t_hi;
        pB0 = (const char*)g_w1t_hi + (((size_t)e * NTOT + n0 + lr0) * KTOT) * 2 + lc * 16;
        pB1 = (const char*)g_w1t_hi + (((size_t)e * NTOT + n0 + lr1) * KTOT) * 2 + lc * 16;
    } else {
        dA = (const char*)g_hlo - (const char*)g_hhi;
        pA0 = (const char*)g_hhi + ((size_t)(m0 + lr0) * HH) * 2 + lc * 16;
        pA1 = (const char*)g_hhi + ((size_t)(m0 + lr1) * HH) * 2 + lc * 16;
        dB = (const char*)g_w2t_lo - (const char*)g_w2t_hi;
        pB0 = (const char*)g_w2t_hi + (((size_t)e * NTOT + n0 + lr0) * KTOT) * 2 + lc * 16;
        pB1 = (const char*)g_w2t_hi + (((size_t)e * NTOT + n0 + lr1) * KTOT) * 2 + lc * 16;
    }
    uint32_t d0 = (uint32_t)(lr0 * 64 + ((lc ^ ((lr0 >> 1) & 3)) << 4));
    uint32_t d1 = (uint32_t)(lr1 * 64 + ((lc ^ ((lr1 >> 1) & 3)) << 4));

    // ---- ldmatrix per-lane offsets ----
    int rA = wr * 64 + (lane & 15);
    int selA = (rA >> 1) & 3;
    uint32_t offA[2];
#pragma unroll
    for (int kk = 0; kk < 2; kk++) {
        int c = kk * 2 + (lane >> 4);
        offA[kk] = (uint32_t)(rA * 64 + ((c ^ selA) << 4));
    }
    int rB = wc * 32 + (lane & 7) + ((lane >> 4) & 1) * 8;
    int selB = (rB >> 1) & 3;
    uint32_t offB[2];
#pragma unroll
    for (int kk = 0; kk < 2; kk++) {
        int c = kk * 2 + ((lane >> 3) & 1);
        offB[kk] = (uint32_t)(rB * 64 + ((c ^ selB) << 4));
    }

    float acc[4][4][4];
#pragma unroll
    for (int i = 0; i < 4; i++)
#pragma unroll
        for (int j = 0; j < 4; j++)
#pragma unroll
            for (int q = 0; q < 4; q++) acc[i][j][q] = 0.f;

    auto LOAD = [&](int ch) {
        uint32_t st = sb + (uint32_t)(ch % 3) * STAGE_B;
        long long ko = (long long)ch * 64;          // KC elems * 2B
        CPA(st + d0,         pA0 + ko,      szA0);
        CPA(st + 8192 + d0,  pA0 + dA + ko, szA0);
        CPA(st + d1,         pA1 + ko,      szA1);
        CPA(st + 8192 + d1,  pA1 + dA + ko, szA1);
        CPA(st + 16384 + d0, pB0 + ko,      16u);
        CPA(st + 24576 + d0, pB0 + dB + ko, 16u);
        CPA(st + 16384 + d1, pB1 + ko,      16u);
        CPA(st + 24576 + d1, pB1 + dB + ko, 16u);
        CPA_COMMIT();
    };

    LOAD(0);
    LOAD(1);
    for (int ch = 0; ch < NC; ch++) {
        if (ch < NC - 1) { CPA_WAIT1(); } else { CPA_WAIT0(); }
        __syncthreads();
        if (ch + 2 < NC) LOAD(ch + 2);
        uint32_t st = sb + (uint32_t)(ch % 3) * STAGE_B;
#pragma unroll
        for (int kk = 0; kk < 2; kk++) {
            uint32_t bh[8], bl[8];
            LDSM4(bh[0], bh[1], bh[2], bh[3], st + 16384 + offB[kk]);
            LDSM4(bh[4], bh[5], bh[6], bh[7], st + 16384 + offB[kk] + 1024);
            LDSM4(bl[0], bl[1], bl[2], bl[3], st + 24576 + offB[kk]);
            LDSM4(bl[4], bl[5], bl[6], bl[7], st + 24576 + offB[kk] + 1024);
#pragma unroll
            for (int i = 0; i < 4; i++) {
                uint32_t ah[4], al[4];
                LDSM4(ah[0], ah[1], ah[2], ah[3], st + offA[kk] + (uint32_t)i * 1024);
                LDSM4(al[0], al[1], al[2], al[3], st + 8192 + offA[kk] + (uint32_t)i * 1024);
#pragma unroll
                for (int j = 0; j < 4; j++) {
                    int i0 = (j >> 1) * 4 + (j & 1) * 2, i1 = i0 + 1;
                    MMA_OP(acc[i][j], ah[0], ah[1], ah[2], ah[3], bh[i0], bh[i1]);
                    MMA_OP(acc[i][j], ah[0], ah[1], ah[2], ah[3], bl[i0], bl[i1]);
                    MMA_OP(acc[i][j], al[0], al[1], al[2], al[3], bh[i0], bh[i1]);
                }
            }
        }
    }

    // ---- epilogue ----
    int g = lane >> 2, tg = lane & 3;
    const float* bias = bias_g + (size_t)e * NTOT + n0;
#pragma unroll
    for (int i = 0; i < 4; i++) {
        int r0 = m0 + wr * 64 + i * 16 + g;
#pragma unroll
        for (int j = 0; j < 4; j++) {
            int nc = wc * 32 + j * 8 + tg * 2;
            float b0v = bias[nc], b1v = bias[nc + 1];
            float2 v0, v1;
            v0.x = acc[i][j][0] + b0v; v0.y = acc[i][j][1] + b1v;
            v1.x = acc[i][j][2] + b0v; v1.y = acc[i][j][3] + b1v;
            if (FIRST) {
                v0.x = fmaxf(v0.x, 0.f); v0.y = fmaxf(v0.y, 0.f);
                v1.x = fmaxf(v1.x, 0.f); v1.y = fmaxf(v1.y, 0.f);
                __nv_bfloat162 h0 = __floats2bfloat162_rn(v0.x, v0.y);
                __nv_bfloat162 h1 = __floats2bfloat162_rn(v1.x, v1.y);
                float2 hf0 = __bfloat1622float2(h0);
                float2 hf1 = __bfloat1622float2(h1);
                __nv_bfloat162 l0 = __floats2bfloat162_rn(v0.x - hf0.x, v0.y - hf0.y);
                __nv_bfloat162 l1 = __floats2bfloat162_rn(v1.x - hf1.x, v1.y - hf1.y);
                size_t o0 = (size_t)r0 * HH + n0 + nc;
                size_t o1 = (size_t)(r0 + 8) * HH + n0 + nc;
                *(__nv_bfloat162*)(g_hhi + o0) = h0;
                *(__nv_bfloat162*)(g_hlo + o0) = l0;
                *(__nv_bfloat162*)(g_hhi + o1) = h1;
                *(__nv_bfloat162*)(g_hlo + o1) = l1;
            } else {
                *(float2*)(g_o + (size_t)r0 * DD + n0 + nc)       = v0;
                *(float2*)(g_o + (size_t)(r0 + 8) * DD + n0 + nc) = v1;
            }
        }
    }
}

// ---------------- combine: y = om + log(gm + gn*exp(on-om)) ----------------
__global__ void combine_k(float* __restrict__ y) {
    int idx = blockIdx.x * 256 + threadIdx.x;
    int b = idx >> 10;
    int d = idx & 1023;
    int p0 = g_pair_pos[b*2], p1 = g_pair_pos[b*2+1];
    float g0 = g_tok_gate[b*2], g1 = g_tok_gate[b*2+1];
    float o0 = g_o[(size_t)p0 * DD + d];
    float o1 = g_o[(size_t)p1 * DD + d];
    float om = fmaxf(o0, o1), on = fminf(o0, o1);
    float gm = (o0 >= o1) ? g0 : g1;
    float gn = (o0 >= o1) ? g1 : g0;
    y[idx] = om + __logf(fmaf(gn, __expf(on - om), gm));
}

// ---------------- balancing loss ----------------
__global__ void loss_k(const float* __restrict__ loss_coef, float* __restrict__ out,
                       int out_size) {
    __shared__ float s_imp[256 * NE];
    __shared__ float s_cnt[256 * NE];
    int t = threadIdx.x;
    float imp[NE], cnt[NE];
#pragma unroll
    for (int e = 0; e < NE; e++) { imp[e] = 0.f; cnt[e] = 0.f; }
    for (int b = t; b < NT; b += 256) {
#pragma unroll
        for (int s = 0; s < 2; s++) {
            int e = g_tok_expert[b*2+s];
            imp[e] += g_tok_gate[b*2+s];
            cnt[e] += 1.f;
        }
    }
#pragma unroll
    for (int e = 0; e < NE; e++) { s_imp[t*NE+e] = imp[e]; s_cnt[t*NE+e] = cnt[e]; }
    __syncthreads();
    for (int stride = 128; stride; stride >>= 1) {
        if (t < stride) {
#pragma unroll
            for (int e = 0; e < NE; e++) {
                s_imp[t*NE+e] += s_imp[(t+stride)*NE+e];
                s_cnt[t*NE+e] += s_cnt[(t+stride)*NE+e];
            }
        }
        __syncthreads();
    }
    if (t == 0) {
        float cv2[2];
        for (int which = 0; which < 2; which++) {
            const float* v = which == 0 ? s_imp : s_cnt;
            float mean = 0.f;
            for (int e = 0; e < NE; e++) mean += v[e];
            mean /= (float)NE;
            float var = 0.f;
            for (int e = 0; e < NE; e++) { float d = v[e] - mean; var += d * d; }
            var /= (float)(NE - 1);
            cv2[which] = var / (mean * mean + 1e-10f);
        }
        float loss = (cv2[0] + cv2[1]) * loss_coef[0];
        if (out_size > NT * DD) out[NT * DD] = loss;
    }
}

// ---------------- launch ----------------
extern "C" void kernel_launch(void* const* d_in, const int* in_sizes, int n_in,
                              void* d_out, int out_size) {
    const float* x  = (const float*)d_in[0];
    const float* wg = (const float*)d_in[1];
    const float* W1 = (const float*)d_in[2];
    const float* b1 = (const float*)d_in[3];
    const float* W2 = (const float*)d_in[4];
    const float* b2 = (const float*)d_in[5];
    const float* lc = (const float*)d_in[6];
    float* out = (float*)d_out;

    cudaFuncSetAttribute(gemm_cp<true>,  cudaFuncAttributeMaxDynamicSharedMemorySize, SMEM_G);
    cudaFuncSetAttribute(gemm_cp<false>, cudaFuncAttributeMaxDynamicSharedMemorySize, SMEM_G);

    init_k<<<1, 32>>>();
    gate_k<<<512, 256>>>(x, wg);
    offsets_k<<<1, 256>>>();
    scatter_k<<<16, 256>>>();
    xsplit_k<<<(NT * DD) / 1024, 256>>>(x);
    trans_split_k<true ><<<dim3(HH/32, DD/32, NE), dim3(32, 8)>>>(W1);
    trans_split_k<false><<<dim3(DD/32, HH/32, NE), dim3(32, 8)>>>(W2);
    gemm_cp<true ><<<dim3(HH/128, NTILES), 256, SMEM_G>>>(b1);
    gemm_cp<false><<<dim3(DD/128, NTILES), 256, SMEM_G>>>(b2);
    combine_k<<<(NT * DD) / 256, 256>>>(out);
    loss_k<<<1, 256>>>(lc, out, out_size);
}

// round 12
// speedup vs baseline: 2.6982x; 1.0185x over previous
#include <cuda_runtime.h>
#include <cuda_bf16.h>
#include <math.h>
#include <stdint.h>

#define NT 4096
#define DD 1024
#define HH 4096
#define NE 8
#define TILE_M 128
#define TILE_N 256
#define MAXPAIRS (NT*2 + NE*TILE_M)   // 9216
#define NTILES (MAXPAIRS/TILE_M)      // 72
#define KC 32                          // K elements per chunk
#define STAGE_B 49152                  // A_hi 8K | A_lo 8K | B_hi 16K | B_lo 16K
#define SMEM_G (4*STAGE_B)             // 196608

// ---------------- scratch ----------------
__device__ __nv_bfloat16 g_xhi[(size_t)NT * DD];
__device__ __nv_bfloat16 g_xlo[(size_t)NT * DD];
__device__ __nv_bfloat16 g_hhi[(size_t)MAXPAIRS * HH];
__device__ __nv_bfloat16 g_hlo[(size_t)MAXPAIRS * HH];
__device__ float g_o[(size_t)MAXPAIRS * DD];
__device__ __nv_bfloat16 g_w1t_hi[(size_t)NE * HH * DD];  // [E][N=H][K=D]
__device__ __nv_bfloat16 g_w1t_lo[(size_t)NE * HH * DD];
__device__ __nv_bfloat16 g_w2t_hi[(size_t)NE * DD * HH];  // [E][N=D][K=H]
__device__ __nv_bfloat16 g_w2t_lo[(size_t)NE * DD * HH];
__device__ int   g_tok_expert[NT*2];
__device__ float g_tok_gate[NT*2];
__device__ int   g_pair_pos[NT*2];
__device__ int   g_pair_token[MAXPAIRS];
__device__ int   g_counts[NE];
__device__ int   g_cursor[NE];
__device__ int   g_offsets[NE+1];
__device__ int   g_tile_expert[NTILES];

// ---------------- asm helpers ----------------
__device__ __forceinline__ uint32_t smem_u32(const void* p) {
    uint32_t a;
    asm("{ .reg .u64 t; cvta.to.shared.u64 t, %1; cvt.u32.u64 %0, t; }" : "=r"(a) : "l"(p));
    return a;
}
#define CPA(dst, src, sz) \
    asm volatile("cp.async.cg.shared.global [%0], [%1], 16, %2;" \
        :: "r"(dst), "l"(src), "r"(sz))
#define CPA_COMMIT() asm volatile("cp.async.commit_group;")
#define CPA_WAIT2()  asm volatile("cp.async.wait_group 2;")
#define CPA_WAIT1()  asm volatile("cp.async.wait_group 1;")
#define CPA_WAIT0()  asm volatile("cp.async.wait_group 0;")
#define LDSM4(r0,r1,r2,r3, a) \
    asm volatile("ldmatrix.sync.aligned.m8n8.x4.shared.b16 {%0,%1,%2,%3}, [%4];" \
        : "=r"(r0), "=r"(r1), "=r"(r2), "=r"(r3) : "r"(a))
#define MMA_OP(c, a0,a1,a2,a3, b0,b1) \
  asm volatile("mma.sync.aligned.m16n8k16.row.col.f32.bf16.bf16.f32 " \
    "{%0,%1,%2,%3}, {%4,%5,%6,%7}, {%8,%9}, {%0,%1,%2,%3};" \
    : "+f"((c)[0]), "+f"((c)[1]), "+f"((c)[2]), "+f"((c)[3]) \
    : "r"(a0), "r"(a1), "r"(a2), "r"(a3), "r"(b0), "r"(b1))

// ---------------- small kernels ----------------
__global__ void init_k() {
    int t = threadIdx.x;
    if (t < NE) { g_counts[t] = 0; g_cursor[t] = 0; }
}

__global__ void gate_k(const float* __restrict__ x, const float* __restrict__ wg) {
    __shared__ float s_wg[DD * NE];
    for (int i = threadIdx.x; i < DD * NE; i += 256) s_wg[i] = wg[i];
    __syncthreads();
    int warp = threadIdx.x >> 5, lane = threadIdx.x & 31;
    int b = blockIdx.x * 8 + warp;
    const float* xr = x + (size_t)b * DD;
    float acc[NE];
#pragma unroll
    for (int e = 0; e < NE; e++) acc[e] = 0.f;
    for (int k = lane; k < DD; k += 32) {
        float xv = xr[k];
        const float* w = &s_wg[k * NE];
#pragma unroll
        for (int e = 0; e < NE; e++) acc[e] += xv * w[e];
    }
#pragma unroll
    for (int e = 0; e < NE; e++) {
#pragma unroll
        for (int o = 16; o; o >>= 1) acc[e] += __shfl_xor_sync(0xffffffffu, acc[e], o);
    }
    if (lane == 0) {
        int i0 = 0; float l0 = acc[0];
#pragma unroll
        for (int e = 1; e < NE; e++) if (acc[e] > l0) { l0 = acc[e]; i0 = e; }
        int i1 = -1; float l1 = -3.4e38f;
#pragma unroll
        for (int e = 0; e < NE; e++) if (e != i0 && acc[e] > l1) { l1 = acc[e]; i1 = e; }
        float e1  = expf(l1 - l0);
        float inv = 1.f / (1.f + e1);
        g_tok_expert[b*2] = i0;  g_tok_expert[b*2+1] = i1;
        g_tok_gate[b*2]   = inv; g_tok_gate[b*2+1]   = e1 * inv;
        atomicAdd(&g_counts[i0], 1);
        atomicAdd(&g_counts[i1], 1);
    }
}

__global__ void offsets_k() {
    int t = threadIdx.x;
    for (int i = t; i < MAXPAIRS; i += 256) g_pair_token[i] = -1;
    __syncthreads();
    if (t == 0) {
        int off = 0;
        for (int e = 0; e < NE; e++) {
            g_offsets[e] = off;
            int ct = (g_counts[e] + TILE_M - 1) / TILE_M;
            for (int it = 0; it < ct; it++) g_tile_expert[off / TILE_M + it] = e;
            off += ct * TILE_M;
        }
        g_offsets[NE] = off;
        for (int it = off / TILE_M; it < NTILES; it++) g_tile_expert[it] = -1;
    }
}

__global__ void scatter_k() {
    int b = blockIdx.x * blockDim.x + threadIdx.x;
    if (b >= NT) return;
#pragma unroll
    for (int s = 0; s < 2; s++) {
        int e = g_tok_expert[b*2+s];
        int p = atomicAdd(&g_cursor[e], 1);
        int row = g_offsets[e] + p;
        g_pair_token[row] = b;
        g_pair_pos[b*2+s] = row;
    }
}

// ---------------- x hi/lo split ----------------
__global__ void xsplit_k(const float* __restrict__ x) {
    int idx = blockIdx.x * 256 + threadIdx.x;       // * 4 floats
    float4 v = ((const float4*)x)[idx];
    __nv_bfloat162 h01 = __floats2bfloat162_rn(v.x, v.y);
    __nv_bfloat162 h23 = __floats2bfloat162_rn(v.z, v.w);
    float2 f01 = __bfloat1622float2(h01);
    float2 f23 = __bfloat1622float2(h23);
    __nv_bfloat162 l01 = __floats2bfloat162_rn(v.x - f01.x, v.y - f01.y);
    __nv_bfloat162 l23 = __floats2bfloat162_rn(v.z - f23.x, v.w - f23.y);
    ((uint2*)g_xhi)[idx] = make_uint2(*(uint32_t*)&h01, *(uint32_t*)&h23);
    ((uint2*)g_xlo)[idx] = make_uint2(*(uint32_t*)&l01, *(uint32_t*)&l23);
}

// ------- weight transpose + hi/lo split: [E][K][N] f32 -> [E][N][K] bf16, vectorized -------
template<bool W1SEL>
__global__ __launch_bounds__(256)
void trans_split_k(const float* __restrict__ in) {
    constexpr int K = W1SEL ? DD : HH;
    constexpr int N = W1SEL ? HH : DD;
    __nv_bfloat16* ohi = W1SEL ? g_w1t_hi : g_w2t_hi;
    __nv_bfloat16* olo = W1SEL ? g_w1t_lo : g_w2t_lo;
    __shared__ float tile[64][65];
    int e = blockIdx.z;
    int k0 = blockIdx.y * 64, n0 = blockIdx.x * 64;
    int t = threadIdx.x;
    {   // load 64x64 f32, coalesced along N (float4)
        int tx = t & 15, ty = t >> 4;
        const float* src = in + ((size_t)e * K + k0) * N + n0;
#pragma unroll
        for (int ii = 0; ii < 4; ii++) {
            float4 v = *(const float4*)(src + (size_t)(ty + ii * 16) * N + tx * 4);
            tile[ty + ii * 16][tx * 4 + 0] = v.x;
            tile[ty + ii * 16][tx * 4 + 1] = v.y;
            tile[ty + ii * 16][tx * 4 + 2] = v.z;
            tile[ty + ii * 16][tx * 4 + 3] = v.w;
        }
    }
    __syncthreads();
    // store transposed: coalesced along K, uint4 = 8 bf16
    int tx = t & 7, ty = t >> 3;
    size_t ob = ((size_t)e * N + n0) * K + k0;
#pragma unroll
    for (int jj = 0; jj < 2; jj++) {
        int n = ty + jj * 32;
        uint32_t h[4], l[4];
#pragma unroll
        for (int q = 0; q < 4; q++) {
            float a = tile[tx * 8 + q * 2][n];
            float b = tile[tx * 8 + q * 2 + 1][n];
            __nv_bfloat162 hh = __floats2bfloat162_rn(a, b);
            float2 hf = __bfloat1622float2(hh);
            __nv_bfloat162 ll = __floats2bfloat162_rn(a - hf.x, b - hf.y);
            h[q] = *(uint32_t*)&hh;
            l[q] = *(uint32_t*)&ll;
        }
        *(uint4*)(ohi + ob + (size_t)n * K + tx * 8) = make_uint4(h[0], h[1], h[2], h[3]);
        *(uint4*)(olo + ob + (size_t)n * K + tx * 8) = make_uint4(l[0], l[1], l[2], l[3]);
    }
}

// ---------------- cp.async + ldmatrix grouped GEMM, tile 128x256 ----------------
// stage layout (48KB): A_hi[128][64B] @0 | A_lo @8192 | B_hi[256][64B] @16384 | B_lo @32768
// 16B-slot swizzle: byte = row*64 + ((c ^ ((row>>1)&3))<<4)
template<bool FIRST>
__global__ __launch_bounds__(256, 1)
void gemm_cp(const float* __restrict__ bias_g) {
    constexpr int KTOT = FIRST ? DD : HH;
    constexpr int NTOT = FIRST ? HH : DD;
    constexpr int NC = KTOT / KC;
    int mt = blockIdx.y;
    int e = g_tile_expert[mt];
    if (e < 0) return;

    extern __shared__ char sm[];
    uint32_t sb = smem_u32(sm);
    int tid = threadIdx.x, lane = tid & 31, w = tid >> 5;
    int wr = w >> 2, wc = w & 3;                 // warp grid 2x4, warp tile 64x64
    int m0 = mt * TILE_M, n0 = blockIdx.x * TILE_N;

    // ---- loader setup ----
    int r0 = tid >> 2, lc = tid & 3;             // A rows r0, r0+64; B rows r0+64*jj
    uint32_t dsw = (uint32_t)(r0 * 64 + ((lc ^ ((r0 >> 1) & 3)) << 4));
    const char *pA0, *pA1, *pB;
    uint32_t szA0 = 16, szA1 = 16;
    long long dAlo, dBlo;
    if (FIRST) {
        dAlo = (const char*)g_xlo - (const char*)g_xhi;
        int t0 = g_pair_token[m0 + r0], t1 = g_pair_token[m0 + r0 + 64];
        pA0 = (const char*)g_xhi + ((t0 >= 0 ? (size_t)t0 : 0) * DD) * 2 + lc * 16;
        pA1 = (const char*)g_xhi + ((t1 >= 0 ? (size_t)t1 : 0) * DD) * 2 + lc * 16;
        if (t0 < 0) szA0 = 0;
        if (t1 < 0) szA1 = 0;
        dBlo = (const char*)g_w1t_lo - (const char*)g_w1t_hi;
        pB = (const char*)g_w1t_hi + (((size_t)e * NTOT + n0 + r0) * KTOT) * 2 + lc * 16;
    } else {
        dAlo = (const char*)g_hlo - (const char*)g_hhi;
        pA0 = (const char*)g_hhi + ((size_t)(m0 + r0) * HH) * 2 + lc * 16;
        pA1 = (const char*)g_hhi + ((size_t)(m0 + r0 + 64) * HH) * 2 + lc * 16;
        dBlo = (const char*)g_w2t_lo - (const char*)g_w2t_hi;
        pB = (const char*)g_w2t_hi + (((size_t)e * NTOT + n0 + r0) * KTOT) * 2 + lc * 16;
    }
    const long long bstep = (long long)64 * KTOT * 2;   // 64 B-rows

    // ---- ldmatrix per-lane offsets ----
    int rA = wr * 64 + (lane & 15);
    int selA = (rA >> 1) & 3;
    uint32_t offA[2];
#pragma unroll
    for (int kk = 0; kk < 2; kk++) {
        int c = kk * 2 + (lane >> 4);
        offA[kk] = (uint32_t)(rA * 64 + ((c ^ selA) << 4));
    }
    int rB = wc * 64 + (lane & 7) + ((lane >> 4) & 1) * 8;
    int selB = (rB >> 1) & 3;
    uint32_t offB[2];
#pragma unroll
    for (int kk = 0; kk < 2; kk++) {
        int c = kk * 2 + ((lane >> 3) & 1);
        offB[kk] = (uint32_t)(rB * 64 + ((c ^ selB) << 4));
    }

    float acc[4][8][4];
#pragma unroll
    for (int i = 0; i < 4; i++)
#pragma unroll
        for (int j = 0; j < 8; j++)
#pragma unroll
            for (int q = 0; q < 4; q++) acc[i][j][q] = 0.f;

    auto LOAD = [&](int ch) {
        uint32_t st = sb + (uint32_t)(ch & 3) * STAGE_B;
        long long ko = (long long)ch * 64;       // KC elems * 2B
        CPA(st + dsw,          pA0 + ko,        szA0);
        CPA(st + 8192 + dsw,   pA0 + dAlo + ko, szA0);
        CPA(st + 4096 + dsw,   pA1 + ko,        szA1);
        CPA(st + 12288 + dsw,  pA1 + dAlo + ko, szA1);
#pragma unroll
        for (int jj = 0; jj < 4; jj++) {
            const char* pb = pB + (long long)jj * bstep + ko;
            CPA(st + 16384 + dsw + jj * 4096, pb,        16u);
            CPA(st + 32768 + dsw + jj * 4096, pb + dBlo, 16u);
        }
        CPA_COMMIT();
    };

    LOAD(0); LOAD(1); LOAD(2);
    for (int ch = 0; ch < NC; ch++) {
        if (ch < NC - 2) { CPA_WAIT2(); }
        else if (ch == NC - 2) { CPA_WAIT1(); }
        else { CPA_WAIT0(); }
        __syncthreads();
        if (ch + 3 < NC) LOAD(ch + 3);
        uint32_t st = sb + (uint32_t)(ch & 3) * STAGE_B;
#pragma unroll
        for (int kk = 0; kk < 2; kk++) {
            uint32_t bh[16], bl[16];
#pragma unroll
            for (int jj = 0; jj < 4; jj++) {
                LDSM4(bh[jj*4+0], bh[jj*4+1], bh[jj*4+2], bh[jj*4+3],
                      st + 16384 + offB[kk] + (uint32_t)jj * 1024u);
                LDSM4(bl[jj*4+0], bl[jj*4+1], bl[jj*4+2], bl[jj*4+3],
                      st + 32768 + offB[kk] + (uint32_t)jj * 1024u);
            }
#pragma unroll
            for (int i = 0; i < 4; i++) {
                uint32_t ah[4], al[4];
                LDSM4(ah[0], ah[1], ah[2], ah[3], st + offA[kk] + (uint32_t)i * 1024u);
                LDSM4(al[0], al[1], al[2], al[3], st + 8192 + offA[kk] + (uint32_t)i * 1024u);
#pragma unroll
                for (int j = 0; j < 8; j++) {
                    int i0 = (j >> 1) * 4 + (j & 1) * 2, i1 = i0 + 1;
                    MMA_OP(acc[i][j], ah[0], ah[1], ah[2], ah[3], bh[i0], bh[i1]);
                    MMA_OP(acc[i][j], ah[0], ah[1], ah[2], ah[3], bl[i0], bl[i1]);
                    MMA_OP(acc[i][j], al[0], al[1], al[2], al[3], bh[i0], bh[i1]);
                }
            }
        }
    }

    // ---- epilogue ----
    int g = lane >> 2, tg = lane & 3;
    const float* bias = bias_g + (size_t)e * NTOT + n0 + wc * 64;
#pragma unroll
    for (int i = 0; i < 4; i++) {
        int row = m0 + wr * 64 + i * 16 + g;
#pragma unroll
        for (int j = 0; j < 8; j++) {
            int nc = (j >> 1) * 16 + (j & 1) * 8 + tg * 2;
            float b0v = bias[nc], b1v = bias[nc + 1];
            float2 v0, v1;
            v0.x = acc[i][j][0] + b0v; v0.y = acc[i][j][1] + b1v;
            v1.x = acc[i][j][2] + b0v; v1.y = acc[i][j][3] + b1v;
            size_t col = (size_t)(n0 + wc * 64 + nc);
            if (FIRST) {
                v0.x = fmaxf(v0.x, 0.f); v0.y = fmaxf(v0.y, 0.f);
                v1.x = fmaxf(v1.x, 0.f); v1.y = fmaxf(v1.y, 0.f);
                __nv_bfloat162 h0 = __floats2bfloat162_rn(v0.x, v0.y);
                __nv_bfloat162 h1 = __floats2bfloat162_rn(v1.x, v1.y);
                float2 hf0 = __bfloat1622float2(h0);
                float2 hf1 = __bfloat1622float2(h1);
                __nv_bfloat162 l0 = __floats2bfloat162_rn(v0.x - hf0.x, v0.y - hf0.y);
                __nv_bfloat162 l1 = __floats2bfloat162_rn(v1.x - hf1.x, v1.y - hf1.y);
                size_t o0 = (size_t)row * HH + col;
                size_t o1 = (size_t)(row + 8) * HH + col;
                *(__nv_bfloat162*)(g_hhi + o0) = h0;
                *(__nv_bfloat162*)(g_hlo + o0) = l0;
                *(__nv_bfloat162*)(g_hhi + o1) = h1;
                *(__nv_bfloat162*)(g_hlo + o1) = l1;
            } else {
                *(float2*)(g_o + (size_t)row * DD + col)       = v0;
                *(float2*)(g_o + (size_t)(row + 8) * DD + col) = v1;
            }
        }
    }
}

// ---------------- combine: y = om + log(gm + gn*exp(on-om)) ----------------
__global__ void combine_k(float* __restrict__ y) {
    int idx = blockIdx.x * 256 + threadIdx.x;
    int b = idx >> 10;
    int d = idx & 1023;
    int p0 = g_pair_pos[b*2], p1 = g_pair_pos[b*2+1];
    float g0 = g_tok_gate[b*2], g1 = g_tok_gate[b*2+1];
    float o0 = g_o[(size_t)p0 * DD + d];
    float o1 = g_o[(size_t)p1 * DD + d];
    float om = fmaxf(o0, o1), on = fminf(o0, o1);
    float gm = (o0 >= o1) ? g0 : g1;
    float gn = (o0 >= o1) ? g1 : g0;
    y[idx] = om + __logf(fmaf(gn, __expf(on - om), gm));
}

// ---------------- balancing loss ----------------
__global__ void loss_k(const float* __restrict__ loss_coef, float* __restrict__ out,
                       int out_size) {
    __shared__ float s_imp[256 * NE];
    __shared__ float s_cnt[256 * NE];
    int t = threadIdx.x;
    float imp[NE], cnt[NE];
#pragma unroll
    for (int e = 0; e < NE; e++) { imp[e] = 0.f; cnt[e] = 0.f; }
    for (int b = t; b < NT; b += 256) {
#pragma unroll
        for (int s = 0; s < 2; s++) {
            int e = g_tok_expert[b*2+s];
            imp[e] += g_tok_gate[b*2+s];
            cnt[e] += 1.f;
        }
    }
#pragma unroll
    for (int e = 0; e < NE; e++) { s_imp[t*NE+e] = imp[e]; s_cnt[t*NE+e] = cnt[e]; }
    __syncthreads();
    for (int stride = 128; stride; stride >>= 1) {
        if (t < stride) {
#pragma unroll
            for (int e = 0; e < NE; e++) {
                s_imp[t*NE+e] += s_imp[(t+stride)*NE+e];
                s_cnt[t*NE+e] += s_cnt[(t+stride)*NE+e];
            }
        }
        __syncthreads();
    }
    if (t == 0) {
        float cv2[2];
        for (int which = 0; which < 2; which++) {
            const float* v = which == 0 ? s_imp : s_cnt;
            float mean = 0.f;
            for (int e = 0; e < NE; e++) mean += v[e];
            mean /= (float)NE;
            float var = 0.f;
            for (int e = 0; e < NE; e++) { float d = v[e] - mean; var += d * d; }
            var /= (float)(NE - 1);
            cv2[which] = var / (mean * mean + 1e-10f);
        }
        float loss = (cv2[0] + cv2[1]) * loss_coef[0];
        if (out_size > NT * DD) out[NT * DD] = loss;
    }
}

// ---------------- launch ----------------
extern "C" void kernel_launch(void* const* d_in, const int* in_sizes, int n_in,
                              void* d_out, int out_size) {
    const float* x  = (const float*)d_in[0];
    const float* wg = (const float*)d_in[1];
    const float* W1 = (const float*)d_in[2];
    const float* b1 = (const float*)d_in[3];
    const float* W2 = (const float*)d_in[4];
    const float* b2 = (const float*)d_in[5];
    const float* lc = (const float*)d_in[6];
    float* out = (float*)d_out;

    cudaFuncSetAttribute(gemm_cp<true>,  cudaFuncAttributeMaxDynamicSharedMemorySize, SMEM_G);
    cudaFuncSetAttribute(gemm_cp<false>, cudaFuncAttributeMaxDynamicSharedMemorySize, SMEM_G);

    init_k<<<1, 32>>>();
    gate_k<<<512, 256>>>(x, wg);
    offsets_k<<<1, 256>>>();
    scatter_k<<<16, 256>>>();
    xsplit_k<<<(NT * DD) / 1024, 256>>>(x);
    trans_split_k<true ><<<dim3(HH/64, DD/64, NE), 256>>>(W1);
    trans_split_k<false><<<dim3(DD/64, HH/64, NE), 256>>>(W2);
    gemm_cp<true ><<<dim3(HH/TILE_N, NTILES), 256, SMEM_G>>>(b1);
    gemm_cp<false><<<dim3(DD/TILE_N, NTILES), 256, SMEM_G>>>(b2);
    combine_k<<<(NT * DD) / 256, 256>>>(out);
    loss_k<<<1, 256>>>(lc, out, out_size);
}

// round 15
// speedup vs baseline: 2.7122x; 1.0052x over previous
#include <cuda_runtime.h>
#include <cuda_bf16.h>
#include <math.h>
#include <stdint.h>

#define NT 4096
#define DD 1024
#define HH 4096
#define NE 8
#define TILE_M 128
#define TILE_N 256
#define MAXPAIRS (NT*2 + NE*TILE_M)   // 9216
#define NTILES (MAXPAIRS/TILE_M)      // 72
#define KC 32                          // K elements per chunk
#define STAGE_B 49152                  // A_hi 8K | A_lo 8K | B_hi 16K | B_lo 16K
#define SMEM_G (4*STAGE_B)             // 196608

// ---------------- scratch ----------------
__device__ __nv_bfloat16 g_xhi[(size_t)NT * DD];
__device__ __nv_bfloat16 g_xlo[(size_t)NT * DD];
__device__ __nv_bfloat16 g_hhi[(size_t)MAXPAIRS * HH];
__device__ __nv_bfloat16 g_hlo[(size_t)MAXPAIRS * HH];
__device__ float g_o[(size_t)MAXPAIRS * DD];
__device__ __nv_bfloat16 g_w1t_hi[(size_t)NE * HH * DD];  // [E][N=H][K=D]
__device__ __nv_bfloat16 g_w1t_lo[(size_t)NE * HH * DD];
__device__ __nv_bfloat16 g_w2t_hi[(size_t)NE * DD * HH];  // [E][N=D][K=H]
__device__ __nv_bfloat16 g_w2t_lo[(size_t)NE * DD * HH];
__device__ int   g_tok_expert[NT*2];
__device__ float g_tok_gate[NT*2];
__device__ int   g_pair_pos[NT*2];
__device__ int   g_pair_token[MAXPAIRS];
__device__ int   g_offsets[NE+1];
__device__ int   g_tile_expert[NTILES];

// ---------------- asm helpers ----------------
__device__ __forceinline__ uint32_t smem_u32(const void* p) {
    uint32_t a;
    asm("{ .reg .u64 t; cvta.to.shared.u64 t, %1; cvt.u32.u64 %0, t; }" : "=r"(a) : "l"(p));
    return a;
}
#define CPA(dst, src, sz) \
    asm volatile("cp.async.cg.shared.global [%0], [%1], 16, %2;" \
        :: "r"(dst), "l"(src), "r"(sz))
#define CPA_COMMIT() asm volatile("cp.async.commit_group;")
#define CPA_WAIT2()  asm volatile("cp.async.wait_group 2;")
#define CPA_WAIT1()  asm volatile("cp.async.wait_group 1;")
#define CPA_WAIT0()  asm volatile("cp.async.wait_group 0;")
#define LDSM4(r0,r1,r2,r3, a) \
    asm volatile("ldmatrix.sync.aligned.m8n8.x4.shared.b16 {%0,%1,%2,%3}, [%4];" \
        : "=r"(r0), "=r"(r1), "=r"(r2), "=r"(r3) : "r"(a))
#define MMA_OP(c, a0,a1,a2,a3, b0,b1) \
  asm volatile("mma.sync.aligned.m16n8k16.row.col.f32.bf16.bf16.f32 " \
    "{%0,%1,%2,%3}, {%4,%5,%6,%7}, {%8,%9}, {%0,%1,%2,%3};" \
    : "+f"((c)[0]), "+f"((c)[1]), "+f"((c)[2]), "+f"((c)[3]) \
    : "r"(a0), "r"(a1), "r"(a2), "r"(a3), "r"(b0), "r"(b1))

// ---------------- gate + x hi/lo split (fused) ----------------
__global__ void gate_k(const float* __restrict__ x, const float* __restrict__ wg) {
    __shared__ float s_wg[DD * NE];
    for (int i = threadIdx.x; i < DD * NE; i += 256) s_wg[i] = wg[i];
    __syncthreads();
    int warp = threadIdx.x >> 5, lane = threadIdx.x & 31;
    int b = blockIdx.x * 8 + warp;
    const float* xr = x + (size_t)b * DD;
    float acc[NE];
#pragma unroll
    for (int e = 0; e < NE; e++) acc[e] = 0.f;
    for (int k = lane; k < DD; k += 32) {
        float xv = xr[k];
        const float* w = &s_wg[k * NE];
#pragma unroll
        for (int e = 0; e < NE; e++) acc[e] += xv * w[e];
    }
#pragma unroll
    for (int e = 0; e < NE; e++) {
#pragma unroll
        for (int o = 16; o; o >>= 1) acc[e] += __shfl_xor_sync(0xffffffffu, acc[e], o);
    }
    if (lane == 0) {
        int i0 = 0; float l0 = acc[0];
#pragma unroll
        for (int e = 1; e < NE; e++) if (acc[e] > l0) { l0 = acc[e]; i0 = e; }
        int i1 = -1; float l1 = -3.4e38f;
#pragma unroll
        for (int e = 0; e < NE; e++) if (e != i0 && acc[e] > l1) { l1 = acc[e]; i1 = e; }
        float e1  = expf(l1 - l0);
        float inv = 1.f / (1.f + e1);
        g_tok_expert[b*2] = i0;  g_tok_expert[b*2+1] = i1;
        g_tok_gate[b*2]   = inv; g_tok_gate[b*2+1]   = e1 * inv;
    }
    // ---- fused x hi/lo split: this block covers tokens [blockIdx.x*8, +8) ----
    for (int i = threadIdx.x; i < 2048; i += 256) {     // 2048 float4 = 8 tokens
        int idx = blockIdx.x * 2048 + i;
        float4 v = ((const float4*)x)[idx];
        __nv_bfloat162 h01 = __floats2bfloat162_rn(v.x, v.y);
        __nv_bfloat162 h23 = __floats2bfloat162_rn(v.z, v.w);
        float2 f01 = __bfloat1622float2(h01);
        float2 f23 = __bfloat1622float2(h23);
        __nv_bfloat162 l01 = __floats2bfloat162_rn(v.x - f01.x, v.y - f01.y);
        __nv_bfloat162 l23 = __floats2bfloat162_rn(v.z - f23.x, v.w - f23.y);
        ((uint2*)g_xhi)[idx] = make_uint2(*(uint32_t*)&h01, *(uint32_t*)&h23);
        ((uint2*)g_xlo)[idx] = make_uint2(*(uint32_t*)&l01, *(uint32_t*)&l23);
    }
}

// ------- merged weight transpose + hi/lo split (both layers, one launch) -------
// [E][K][N] f32 -> [E][N][K] bf16 hi/lo, 64x64 tiles, vectorized
__global__ __launch_bounds__(256)
void trans_all_k(const float* __restrict__ W1, const float* __restrict__ W2) {
    int bid = blockIdx.x;
    bool w1 = bid < 8192;
    int K, N, e, bx, by;
    const float* in;
    __nv_bfloat16 *ohi, *olo;
    if (w1) {
        K = DD; N = HH;
        e = bid >> 10; int rem = bid & 1023;
        by = rem >> 6; bx = rem & 63;               // 16 x 64
        in = W1; ohi = g_w1t_hi; olo = g_w1t_lo;
    } else {
        bid -= 8192;
        K = HH; N = DD;
        e = bid >> 10; int rem = bid & 1023;
        by = rem >> 4; bx = rem & 15;               // 64 x 16
        in = W2; ohi = g_w2t_hi; olo = g_w2t_lo;
    }
    __shared__ float tile[64][65];
    int k0 = by * 64, n0 = bx * 64;
    int t = threadIdx.x;
    {   // load 64x64 f32, coalesced along N (float4)
        int tx = t & 15, ty = t >> 4;
        const float* src = in + ((size_t)e * K + k0) * N + n0;
#pragma unroll
        for (int ii = 0; ii < 4; ii++) {
            float4 v = *(const float4*)(src + (size_t)(ty + ii * 16) * N + tx * 4);
            tile[ty + ii * 16][tx * 4 + 0] = v.x;
            tile[ty + ii * 16][tx * 4 + 1] = v.y;
            tile[ty + ii * 16][tx * 4 + 2] = v.z;
            tile[ty + ii * 16][tx * 4 + 3] = v.w;
        }
    }
    __syncthreads();
    int tx = t & 7, ty = t >> 3;
    size_t ob = ((size_t)e * N + n0) * K + k0;
#pragma unroll
    for (int jj = 0; jj < 2; jj++) {
        int n = ty + jj * 32;
        uint32_t h[4], l[4];
#pragma unroll
        for (int q = 0; q < 4; q++) {
            float a = tile[tx * 8 + q * 2][n];
            float b = tile[tx * 8 + q * 2 + 1][n];
            __nv_bfloat162 hh = __floats2bfloat162_rn(a, b);
            float2 hf = __bfloat1622float2(hh);
            __nv_bfloat162 ll = __floats2bfloat162_rn(a - hf.x, b - hf.y);
            h[q] = *(uint32_t*)&hh;
            l[q] = *(uint32_t*)&ll;
        }
        *(uint4*)(ohi + ob + (size_t)n * K + tx * 8) = make_uint4(h[0], h[1], h[2], h[3]);
        *(uint4*)(olo + ob + (size_t)n * K + tx * 8) = make_uint4(l[0], l[1], l[2], l[3]);
    }
}

// ------- offsets + scatter (single block; counts computed here, no global atomics) -------
__global__ void offsets_scatter_k() {
    __shared__ int s_cnt[NE];
    __shared__ int s_cur[NE];
    int t = threadIdx.x;
    for (int i = t; i < MAXPAIRS; i += 256) g_pair_token[i] = -1;
    if (t < NE) s_cnt[t] = 0;
    __syncthreads();
    for (int i = t; i < NT * 2; i += 256)
        atomicAdd(&s_cnt[g_tok_expert[i]], 1);
    __syncthreads();
    if (t == 0) {
        int off = 0;
        for (int e = 0; e < NE; e++) {
            g_offsets[e] = off;
            s_cur[e] = off;
            int ct = (s_cnt[e] + TILE_M - 1) / TILE_M;
            for (int it = 0; it < ct; it++) g_tile_expert[off / TILE_M + it] = e;
            off += ct * TILE_M;
        }
        g_offsets[NE] = off;
        for (int it = off / TILE_M; it < NTILES; it++) g_tile_expert[it] = -1;
    }
    __syncthreads();
    for (int i = t; i < NT * 2; i += 256) {
        int e = g_tok_expert[i];
        int p = atomicAdd(&s_cur[e], 1);
        g_pair_token[p] = i >> 1;
        g_pair_pos[i] = p;
    }
}

// ---------------- cp.async + ldmatrix grouped GEMM, tile 128x256 ----------------
template<bool FIRST>
__global__ __launch_bounds__(256, 1)
void gemm_cp(const float* __restrict__ bias_g) {
    constexpr int KTOT = FIRST ? DD : HH;
    constexpr int NTOT = FIRST ? HH : DD;
    constexpr int NC = KTOT / KC;
    int mt = blockIdx.y;
    int e = g_tile_expert[mt];
    if (e < 0) return;

    extern __shared__ char sm[];
    uint32_t sb = smem_u32(sm);
    int tid = threadIdx.x, lane = tid & 31, w = tid >> 5;
    int wr = w >> 2, wc = w & 3;                 // warp grid 2x4, warp tile 64x64
    int m0 = mt * TILE_M, n0 = blockIdx.x * TILE_N;

    int r0 = tid >> 2, lc = tid & 3;
    uint32_t dsw = (uint32_t)(r0 * 64 + ((lc ^ ((r0 >> 1) & 3)) << 4));
    const char *pA0, *pA1, *pB;
    uint32_t szA0 = 16, szA1 = 16;
    long long dAlo, dBlo;
    if (FIRST) {
        dAlo = (const char*)g_xlo - (const char*)g_xhi;
        int t0 = g_pair_token[m0 + r0], t1 = g_pair_token[m0 + r0 + 64];
        pA0 = (const char*)g_xhi + ((t0 >= 0 ? (size_t)t0 : 0) * DD) * 2 + lc * 16;
        pA1 = (const char*)g_xhi + ((t1 >= 0 ? (size_t)t1 : 0) * DD) * 2 + lc * 16;
        if (t0 < 0) szA0 = 0;
        if (t1 < 0) szA1 = 0;
        dBlo = (const char*)g_w1t_lo - (const char*)g_w1t_hi;
        pB = (const char*)g_w1t_hi + (((size_t)e * NTOT + n0 + r0) * KTOT) * 2 + lc * 16;
    } else {
        dAlo = (const char*)g_hlo - (const char*)g_hhi;
        pA0 = (const char*)g_hhi + ((size_t)(m0 + r0) * HH) * 2 + lc * 16;
        pA1 = (const char*)g_hhi + ((size_t)(m0 + r0 + 64) * HH) * 2 + lc * 16;
        dBlo = (const char*)g_w2t_lo - (const char*)g_w2t_hi;
        pB = (const char*)g_w2t_hi + (((size_t)e * NTOT + n0 + r0) * KTOT) * 2 + lc * 16;
    }
    const long long bstep = (long long)64 * KTOT * 2;

    int rA = wr * 64 + (lane & 15);
    int selA = (rA >> 1) & 3;
    uint32_t offA[2];
#pragma unroll
    for (int kk = 0; kk < 2; kk++) {
        int c = kk * 2 + (lane >> 4);
        offA[kk] = (uint32_t)(rA * 64 + ((c ^ selA) << 4));
    }
    int rB = wc * 64 + (lane & 7) + ((lane >> 4) & 1) * 8;
    int selB = (rB >> 1) & 3;
    uint32_t offB[2];
#pragma unroll
    for (int kk = 0; kk < 2; kk++) {
        int c = kk * 2 + ((lane >> 3) & 1);
        offB[kk] = (uint32_t)(rB * 64 + ((c ^ selB) << 4));
    }

    float acc[4][8][4];
#pragma unroll
    for (int i = 0; i < 4; i++)
#pragma unroll
        for (int j = 0; j < 8; j++)
#pragma unroll
            for (int q = 0; q < 4; q++) acc[i][j][q] = 0.f;

    auto LOAD = [&](int ch) {
        uint32_t st = sb + (uint32_t)(ch & 3) * STAGE_B;
        long long ko = (long long)ch * 64;
        CPA(st + dsw,          pA0 + ko,        szA0);
        CPA(st + 8192 + dsw,   pA0 + dAlo + ko, szA0);
        CPA(st + 4096 + dsw,   pA1 + ko,        szA1);
        CPA(st + 12288 + dsw,  pA1 + dAlo + ko, szA1);
#pragma unroll
        for (int jj = 0; jj < 4; jj++) {
            const char* pb = pB + (long long)jj * bstep + ko;
            CPA(st + 16384 + dsw + jj * 4096, pb,        16u);
            CPA(st + 32768 + dsw + jj * 4096, pb + dBlo, 16u);
        }
        CPA_COMMIT();
    };

    LOAD(0); LOAD(1); LOAD(2);
    for (int ch = 0; ch < NC; ch++) {
        if (ch < NC - 2) { CPA_WAIT2(); }
        else if (ch == NC - 2) { CPA_WAIT1(); }
        else { CPA_WAIT0(); }
        __syncthreads();
        if (ch + 3 < NC) LOAD(ch + 3);
        uint32_t st = sb + (uint32_t)(ch & 3) * STAGE_B;
#pragma unroll
        for (int kk = 0; kk < 2; kk++) {
            uint32_t bh[16], bl[16];
#pragma unroll
            for (int jj = 0; jj < 4; jj++) {
                LDSM4(bh[jj*4+0], bh[jj*4+1], bh[jj*4+2], bh[jj*4+3],
                      st + 16384 + offB[kk] + (uint32_t)jj * 1024u);
                LDSM4(bl[jj*4+0], bl[jj*4+1], bl[jj*4+2], bl[jj*4+3],
                      st + 32768 + offB[kk] + (uint32_t)jj * 1024u);
            }
#pragma unroll
            for (int i = 0; i < 4; i++) {
                uint32_t ah[4], al[4];
                LDSM4(ah[0], ah[1], ah[2], ah[3], st + offA[kk] + (uint32_t)i * 1024u);
                LDSM4(al[0], al[1], al[2], al[3], st + 8192 + offA[kk] + (uint32_t)i * 1024u);
#pragma unroll
                for (int j = 0; j < 8; j++) {
                    int i0 = (j >> 1) * 4 + (j & 1) * 2, i1 = i0 + 1;
                    MMA_OP(acc[i][j], ah[0], ah[1], ah[2], ah[3], bh[i0], bh[i1]);
                    MMA_OP(acc[i][j], ah[0], ah[1], ah[2], ah[3], bl[i0], bl[i1]);
                    MMA_OP(acc[i][j], al[0], al[1], al[2], al[3], bh[i0], bh[i1]);
                }
            }
        }
    }

    int g = lane >> 2, tg = lane & 3;
    const float* bias = bias_g + (size_t)e * NTOT + n0 + wc * 64;
#pragma unroll
    for (int i = 0; i < 4; i++) {
        int row = m0 + wr * 64 + i * 16 + g;
#pragma unroll
        for (int j = 0; j < 8; j++) {
            int nc = (j >> 1) * 16 + (j & 1) * 8 + tg * 2;
            float b0v = bias[nc], b1v = bias[nc + 1];
            float2 v0, v1;
            v0.x = acc[i][j][0] + b0v; v0.y = acc[i][j][1] + b1v;
            v1.x = acc[i][j][2] + b0v; v1.y = acc[i][j][3] + b1v;
            size_t col = (size_t)(n0 + wc * 64 + nc);
            if (FIRST) {
                v0.x = fmaxf(v0.x, 0.f); v0.y = fmaxf(v0.y, 0.f);
                v1.x = fmaxf(v1.x, 0.f); v1.y = fmaxf(v1.y, 0.f);
                __nv_bfloat162 h0 = __floats2bfloat162_rn(v0.x, v0.y);
                __nv_bfloat162 h1 = __floats2bfloat162_rn(v1.x, v1.y);
                float2 hf0 = __bfloat1622float2(h0);
                float2 hf1 = __bfloat1622float2(h1);
                __nv_bfloat162 l0 = __floats2bfloat162_rn(v0.x - hf0.x, v0.y - hf0.y);
                __nv_bfloat162 l1 = __floats2bfloat162_rn(v1.x - hf1.x, v1.y - hf1.y);
                size_t o0 = (size_t)row * HH + col;
                size_t o1 = (size_t)(row + 8) * HH + col;
                *(__nv_bfloat162*)(g_hhi + o0) = h0;
                *(__nv_bfloat162*)(g_hlo + o0) = l0;
                *(__nv_bfloat162*)(g_hhi + o1) = h1;
                *(__nv_bfloat162*)(g_hlo + o1) = l1;
            } else {
                *(float2*)(g_o + (size_t)row * DD + col)       = v0;
                *(float2*)(g_o + (size_t)(row + 8) * DD + col) = v1;
            }
        }
    }
}

// ---------------- combine ----------------
__global__ void combine_k(float* __restrict__ y) {
    int idx = blockIdx.x * 256 + threadIdx.x;
    int b = idx >> 10;
    int d = idx & 1023;
    int p0 = g_pair_pos[b*2], p1 = g_pair_pos[b*2+1];
    float g0 = g_tok_gate[b*2], g1 = g_tok_gate[b*2+1];
    float o0 = g_o[(size_t)p0 * DD + d];
    float o1 = g_o[(size_t)p1 * DD + d];
    float om = fmaxf(o0, o1), on = fminf(o0, o1);
    float gm = (o0 >= o1) ? g0 : g1;
    float gn = (o0 >= o1) ? g1 : g0;
    y[idx] = om + __logf(fmaf(gn, __expf(on - om), gm));
}

// ---------------- balancing loss ----------------
__global__ void loss_k(const float* __restrict__ loss_coef, float* __restrict__ out,
                       int out_size) {
    __shared__ float s_imp[256 * NE];
    __shared__ float s_cnt[256 * NE];
    int t = threadIdx.x;
    float imp[NE], cnt[NE];
#pragma unroll
    for (int e = 0; e < NE; e++) { imp[e] = 0.f; cnt[e] = 0.f; }
    for (int b = t; b < NT; b += 256) {
#pragma unroll
        for (int s = 0; s < 2; s++) {
            int e = g_tok_expert[b*2+s];
            imp[e] += g_tok_gate[b*2+s];
            cnt[e] += 1.f;
        }
    }
#pragma unroll
    for (int e = 0; e < NE; e++) { s_imp[t*NE+e] = imp[e]; s_cnt[t*NE+e] = cnt[e]; }
    __syncthreads();
    for (int stride = 128; stride; stride >>= 1) {
        if (t < stride) {
#pragma unroll
            for (int e = 0; e < NE; e++) {
                s_imp[t*NE+e] += s_imp[(t+stride)*NE+e];
                s_cnt[t*NE+e] += s_cnt[(t+stride)*NE+e];
            }
        }
        __syncthreads();
    }
    if (t == 0) {
        float cv2[2];
        for (int which = 0; which < 2; which++) {
            const float* v = which == 0 ? s_imp : s_cnt;
            float mean = 0.f;
            for (int e = 0; e < NE; e++) mean += v[e];
            mean /= (float)NE;
            float var = 0.f;
            for (int e = 0; e < NE; e++) { float d = v[e] - mean; var += d * d; }
            var /= (float)(NE - 1);
            cv2[which] = var / (mean * mean + 1e-10f);
        }
        float loss = (cv2[0] + cv2[1]) * loss_coef[0];
        if (out_size > NT * DD) out[NT * DD] = loss;
    }
}

// ---------------- launch ----------------
extern "C" void kernel_launch(void* const* d_in, const int* in_sizes, int n_in,
                              void* d_out, int out_size) {
    const float* x  = (const float*)d_in[0];
    const float* wg = (const float*)d_in[1];
    const float* W1 = (const float*)d_in[2];
    const float* b1 = (const float*)d_in[3];
    const float* W2 = (const float*)d_in[4];
    const float* b2 = (const float*)d_in[5];
    const float* lc = (const float*)d_in[6];
    float* out = (float*)d_out;

    cudaFuncSetAttribute(gemm_cp<true>,  cudaFuncAttributeMaxDynamicSharedMemorySize, SMEM_G);
    cudaFuncSetAttribute(gemm_cp<false>, cudaFuncAttributeMaxDynamicSharedMemorySize, SMEM_G);

    gate_k<<<512, 256>>>(x, wg);                         // #1 (gate + xsplit)
    trans_all_k<<<16384, 256>>>(W1, W2);                 // #2 (both weight transposes)
    offsets_scatter_k<<<1, 256>>>();                     // #3 (counts + offsets + scatter)
    gemm_cp<true ><<<dim3(HH/TILE_N, NTILES), 256, SMEM_G>>>(b1);   // #4  <- ncu capture slot
    gemm_cp<false><<<dim3(DD/TILE_N, NTILES), 256, SMEM_G>>>(b2);   // #5
    combine_k<<<(NT * DD) / 256, 256>>>(out);            // #6
    loss_k<<<1, 256>>>(lc, out, out_size);               // #7
}